// round 5
// baseline (speedup 1.0000x reference)
#include <cuda_runtime.h>
#include <cstdint>

// ---------------- problem constants ----------------
#define NN    50000
#define INF   512
#define HID   128
#define OUTF  40
#define EE    600000
#define NWX   16      // INF/32 words per row
#define NWH   4       // HID/32 words per row

// ---------------- device scratch (no allocs allowed) ----------------
__device__ float    g_colsum[INF];
__device__ float    g_alpha[3];
__device__ unsigned g_Xs[NN * NWX];
__device__ unsigned g_Xv[NN * NWX];
__device__ unsigned g_w0s[NWX * HID], g_w0v[NWX * HID];
__device__ unsigned g_w1s[NWH * HID], g_w1v[NWH * HID];
__device__ unsigned g_w2s[NWH * OUTF], g_w2v[NWH * OUTF];
__device__ int      g_count[NN];
__device__ int      g_rowptr[NN + 1];
__device__ int      g_cursor[NN];
__device__ float    g_dinv[NN];
__device__ int      g_csrc[EE];
__device__ float    g_cw[EE];
__device__ float    g_h[NN * HID];     // layer activations (pre-aggregation / post-GEMM)
__device__ float    g_h3[NN * OUTF];
__device__ unsigned g_Ss[NN * NWH], g_Sv[NN * NWH];
__device__ int      g_is64;

// ---------------- threefry2x32 (20 rounds, jax-compatible) ----------------
__device__ __forceinline__ void tf2x32_d(unsigned k0, unsigned k1, unsigned c0, unsigned c1,
                                         unsigned& o0, unsigned& o1) {
    unsigned ks2 = k0 ^ k1 ^ 0x1BD11BDAu;
    unsigned x0 = c0 + k0, x1 = c1 + k1;
#define TFR_(r) { x0 += x1; x1 = (x1 << r) | (x1 >> (32 - r)); x1 ^= x0; }
    TFR_(13) TFR_(15) TFR_(26) TFR_(6)  x0 += k1;  x1 += ks2 + 1u;
    TFR_(17) TFR_(29) TFR_(16) TFR_(24) x0 += ks2; x1 += k0 + 2u;
    TFR_(13) TFR_(15) TFR_(26) TFR_(6)  x0 += k0;  x1 += k1 + 3u;
    TFR_(17) TFR_(29) TFR_(16) TFR_(24) x0 += k1;  x1 += ks2 + 4u;
    TFR_(13) TFR_(15) TFR_(26) TFR_(6)  x0 += ks2; x1 += k0 + 5u;
#undef TFR_
    o0 = x0; o1 = x1;
}

static void tf2x32_h(unsigned k0, unsigned k1, unsigned c0, unsigned c1,
                     unsigned& o0, unsigned& o1) {
    unsigned ks2 = k0 ^ k1 ^ 0x1BD11BDAu;
    unsigned x0 = c0 + k0, x1 = c1 + k1;
#define TFRH(r) { x0 += x1; x1 = (x1 << r) | (x1 >> (32 - r)); x1 ^= x0; }
    TFRH(13) TFRH(15) TFRH(26) TFRH(6)  x0 += k1;  x1 += ks2 + 1u;
    TFRH(17) TFRH(29) TFRH(16) TFRH(24) x0 += ks2; x1 += k0 + 2u;
    TFRH(13) TFRH(15) TFRH(26) TFRH(6)  x0 += k0;  x1 += k1 + 3u;
    TFRH(17) TFRH(29) TFRH(16) TFRH(24) x0 += k1;  x1 += ks2 + 4u;
    TFRH(13) TFRH(15) TFRH(26) TFRH(6)  x0 += ks2; x1 += k0 + 5u;
#undef TFRH
    o0 = x0; o1 = x1;
}

// ---------------- edge index access (int32/int64 detected at runtime) ----------------
__device__ __forceinline__ int edge_at(const void* p, int which, int e, int E) {
    if (g_is64) return (int)((const long long*)p)[(size_t)which * E + e];
    return ((const int*)p)[which * E + e];
}

// ---------------- kernels ----------------
__global__ void k_init(const unsigned* eb) {
    int i = blockIdx.x * blockDim.x + threadIdx.x;
    if (i < INF) g_colsum[i] = 0.0f;
    if (i < NN) { g_count[i] = 0; g_cursor[i] = 0; }
    if (i == 0) {
        // int64 iff the high 32-bit word of each (nonneg, <2^31) value is zero
        int ok = 1;
        for (int t = 0; t < 64; t++) if (eb[2 * t + 1] != 0u) { ok = 0; break; }
        g_is64 = ok;
    }
}

__global__ void k_colsum(const float* __restrict__ x) {
    int c = blockIdx.x * 256 + threadIdx.x;           // 2 blocks.x cover 512 cols
    int r0 = blockIdx.y * 500;
    float s = 0.0f;
    for (int r = r0; r < r0 + 500; r++) s += x[r * INF + c];
    atomicAdd(&g_colsum[c], s);
}

__global__ void k_alpha(const float* __restrict__ w0, const float* __restrict__ w1,
                        const float* __restrict__ w2) {
    const float* p; int n;
    if (blockIdx.x == 0)      { p = w0; n = INF * HID; }
    else if (blockIdx.x == 1) { p = w1; n = HID * HID; }
    else                      { p = w2; n = HID * OUTF; }
    float s = 0.0f;
    for (int i = threadIdx.x; i < n; i += 256) s += fabsf(p[i]);
    __shared__ float sh[8];
    for (int off = 16; off; off >>= 1) s += __shfl_xor_sync(0xffffffffu, s, off);
    if ((threadIdx.x & 31) == 0) sh[threadIdx.x >> 5] = s;
    __syncthreads();
    if (threadIdx.x == 0) {
        float t = 0.0f;
        for (int w = 0; w < 8; w++) t += sh[w];
        g_alpha[blockIdx.x] = t;
    }
}

__global__ void k_packw(const float* __restrict__ w0, const float* __restrict__ w1,
                        const float* __restrict__ w2) {
    int b = blockIdx.x, j = threadIdx.x;
    if (b < NWX) {                       // w0: [512,128]
        unsigned sb = 0, vb = 0;
        for (int i = 0; i < 32; i++) {
            float v = w0[(b * 32 + i) * HID + j];
            sb |= (v > 0.0f ? 1u : 0u) << i;
            vb |= (v != 0.0f ? 1u : 0u) << i;
        }
        g_w0s[b * HID + j] = sb; g_w0v[b * HID + j] = vb;
    } else if (b < NWX + NWH) {          // w1: [128,128]
        int w = b - NWX;
        unsigned sb = 0, vb = 0;
        for (int i = 0; i < 32; i++) {
            float v = w1[(w * 32 + i) * HID + j];
            sb |= (v > 0.0f ? 1u : 0u) << i;
            vb |= (v != 0.0f ? 1u : 0u) << i;
        }
        g_w1s[w * HID + j] = sb; g_w1v[w * HID + j] = vb;
    } else {                             // w2: [128,40]
        int w = b - NWX - NWH;
        if (j < OUTF) {
            unsigned sb = 0, vb = 0;
            for (int i = 0; i < 32; i++) {
                float v = w2[(w * 32 + i) * OUTF + j];
                sb |= (v > 0.0f ? 1u : 0u) << i;
                vb |= (v != 0.0f ? 1u : 0u) << i;
            }
            g_w2s[w * OUTF + j] = sb; g_w2v[w * OUTF + j] = vb;
        }
    }
}

__global__ void k_count(const void* __restrict__ ei, int E) {
    int e = blockIdx.x * blockDim.x + threadIdx.x;
    if (e < E) atomicAdd(&g_count[edge_at(ei, 0, e, E)], 1);
}

__global__ void k_scan() {
    __shared__ int warpsum[32];
    __shared__ int s_run;
    int tid = threadIdx.x, l = tid & 31, w = tid >> 5;
    if (tid == 0) s_run = 0;
    __syncthreads();
    for (int base = 0; base < NN; base += 1024) {
        int i = base + tid;
        int v = (i < NN) ? g_count[i] : 0;
        if (i < NN) g_dinv[i] = rsqrtf((float)(v + 1));   // deg includes self-loop, >=1
        int x = v;
        for (int off = 1; off < 32; off <<= 1) {
            int t = __shfl_up_sync(0xffffffffu, x, off);
            if (l >= off) x += t;
        }
        if (l == 31) warpsum[w] = x;
        __syncthreads();
        if (w == 0) {
            int y = warpsum[l];
            for (int off = 1; off < 32; off <<= 1) {
                int t = __shfl_up_sync(0xffffffffu, y, off);
                if (l >= off) y += t;
            }
            warpsum[l] = y;
        }
        __syncthreads();
        int incl = x + ((w > 0) ? warpsum[w - 1] : 0);
        int run = s_run;
        if (i < NN) g_rowptr[i] = run + incl - v;
        __syncthreads();
        if (tid == 1023) s_run = run + incl;
        __syncthreads();
    }
    if (threadIdx.x == 0) g_rowptr[NN] = s_run;
}

__global__ void k_scatter(const void* __restrict__ ei, int E) {
    int e = blockIdx.x * blockDim.x + threadIdx.x;
    if (e < E) {
        int dst = edge_at(ei, 0, e, E);
        int src = edge_at(ei, 1, e, E);
        int p = g_rowptr[dst] + atomicAdd(&g_cursor[dst], 1);
        g_csrc[p] = src;
        g_cw[p] = g_dinv[dst] * g_dinv[src];
    }
}

__global__ void k_packX(const float* __restrict__ x) {
    int wid = threadIdx.x >> 5, l = threadIdx.x & 31;
    int r = blockIdx.x * 8 + wid;
    if (r >= NN) return;
    const float inv_n = 1.0f / (float)NN;
    for (int w = 0; w < NWX; w++) {
        int c = w * 32 + l;
        float t = x[r * INF + c] - g_colsum[c] * inv_n;
        unsigned sb = __ballot_sync(0xffffffffu, t > 0.0f);
        unsigned vb = __ballot_sync(0xffffffffu, t != 0.0f);
        if (l == 0) { g_Xs[r * NWX + w] = sb; g_Xv[r * NWX + w] = vb; }
    }
}

__global__ void k_gemm1() {
    __shared__ unsigned ws[NWX * HID], wv[NWX * HID];
    __shared__ unsigned rs[8 * NWX], rv[8 * NWX];
    int tx = threadIdx.x, ty = threadIdx.y;
    int tid = ty * 128 + tx;
    for (int i = tid; i < NWX * HID; i += 1024) { ws[i] = g_w0s[i]; wv[i] = g_w0v[i]; }
    int r0 = blockIdx.x * 8;
    if (tid < 128) {
        int rr = tid >> 4, w = tid & 15;
        rs[tid] = g_Xs[(r0 + rr) * NWX + w];
        rv[tid] = g_Xv[(r0 + rr) * NWX + w];
    }
    __syncthreads();
    int pos = 0, tot = 0;
#pragma unroll
    for (int w = 0; w < NWX; w++) {
        unsigned a = rs[ty * NWX + w], av = rv[ty * NWX + w];
        unsigned b = ws[w * HID + tx], bv = wv[w * HID + tx];
        unsigned m = av & bv;
        pos += __popc(m & ~(a ^ b));
        tot += __popc(m);
    }
    float alpha = g_alpha[0] * (1.0f / (float)(INF * HID));
    g_h[(r0 + ty) * HID + tx] = alpha * (float)(2 * pos - tot);
}

__global__ void k_gemm2() {
    __shared__ unsigned ws[NWH * HID], wv[NWH * HID];
    __shared__ unsigned rs[8 * NWH], rv[8 * NWH];
    int tx = threadIdx.x, ty = threadIdx.y;
    int tid = ty * 128 + tx;
    for (int i = tid; i < NWH * HID; i += 1024) { ws[i] = g_w1s[i]; wv[i] = g_w1v[i]; }
    int r0 = blockIdx.x * 8;
    if (tid < 32) {
        int rr = tid >> 2, w = tid & 3;
        rs[tid] = g_Ss[(r0 + rr) * NWH + w];
        rv[tid] = g_Sv[(r0 + rr) * NWH + w];
    }
    __syncthreads();
    int pos = 0, tot = 0;
#pragma unroll
    for (int w = 0; w < NWH; w++) {
        unsigned a = rs[ty * NWH + w], av = rv[ty * NWH + w];
        unsigned b = ws[w * HID + tx], bv = wv[w * HID + tx];
        unsigned m = av & bv;
        pos += __popc(m & ~(a ^ b));
        tot += __popc(m);
    }
    float alpha = g_alpha[1] * (1.0f / (float)(HID * HID));
    g_h[(r0 + ty) * HID + tx] = alpha * (float)(2 * pos - tot);
}

__global__ void k_gemm3() {
    __shared__ unsigned ws[NWH * OUTF], wv[NWH * OUTF];
    __shared__ unsigned rs[16 * NWH], rv[16 * NWH];
    int tx = threadIdx.x, ty = threadIdx.y;
    int tid = ty * 40 + tx;
    if (tid < NWH * OUTF) { ws[tid] = g_w2s[tid]; wv[tid] = g_w2v[tid]; }
    int r0 = blockIdx.x * 16;
    if (tid < 64) {
        int rr = tid >> 2, w = tid & 3;
        rs[tid] = g_Ss[(r0 + rr) * NWH + w];
        rv[tid] = g_Sv[(r0 + rr) * NWH + w];
    }
    __syncthreads();
    int pos = 0, tot = 0;
#pragma unroll
    for (int w = 0; w < NWH; w++) {
        unsigned a = rs[ty * NWH + w], av = rv[ty * NWH + w];
        unsigned b = ws[w * OUTF + tx], bv = wv[w * OUTF + tx];
        unsigned m = av & bv;
        pos += __popc(m & ~(a ^ b));
        tot += __popc(m);
    }
    float alpha = g_alpha[2] * (1.0f / (float)(HID * OUTF));
    g_h3[(r0 + ty) * OUTF + tx] = alpha * (float)(2 * pos - tot);
}

// aggregate (128 feats) + bias + dropout(partitionable threefry) + sign + bitpack
__global__ void k_agg_pack(const float* __restrict__ bias, unsigned fk0, unsigned fk1) {
    int wid = threadIdx.x >> 5, l = threadIdx.x & 31;
    int r = blockIdx.x * 8 + wid;
    if (r >= NN) return;
    float dr = g_dinv[r];
    float sw = dr * dr;
    const float* hr = g_h + r * HID;
    float a0 = sw * hr[l], a1 = sw * hr[32 + l], a2 = sw * hr[64 + l], a3 = sw * hr[96 + l];
    int p0 = g_rowptr[r], p1 = g_rowptr[r + 1];
    for (int p = p0; p < p1; p++) {
        int s = __ldg(&g_csrc[p]);
        float w = __ldg(&g_cw[p]);
        const float* hs = g_h + s * HID;
        a0 += w * hs[l]; a1 += w * hs[32 + l]; a2 += w * hs[64 + l]; a3 += w * hs[96 + l];
    }
    a0 += bias[l]; a1 += bias[32 + l]; a2 += bias[64 + l]; a3 += bias[96 + l];
    float av[4] = {a0, a1, a2, a3};
    unsigned base = (unsigned)(r * HID);
#pragma unroll
    for (int k = 0; k < 4; k++) {
        unsigned idx = base + (unsigned)(k * 32 + l);
        unsigned o0, o1;
        tf2x32_d(fk0, fk1, 0u, idx, o0, o1);
        unsigned bits = o0 ^ o1;                // jax partitionable 32-bit path
        bool keep = (bits >> 31) == 0u;         // uniform < 0.5
        float v = av[k];
        unsigned sb = __ballot_sync(0xffffffffu, v > 0.0f);
        unsigned vb = __ballot_sync(0xffffffffu, keep && (v != 0.0f));
        if (l == 0) { g_Ss[r * NWH + k] = sb; g_Sv[r * NWH + k] = vb; }
    }
}

// final aggregate (40 feats) + bias + log_softmax
__global__ void k_agg_final(const float* __restrict__ bias, float* __restrict__ out) {
    int wid = threadIdx.x >> 5, l = threadIdx.x & 31;
    int r = blockIdx.x * 8 + wid;
    if (r >= NN) return;
    float dr = g_dinv[r];
    float sw = dr * dr;
    const float* hr = g_h3 + r * OUTF;
    float a0 = sw * hr[l];
    float a1 = (l < 8) ? sw * hr[32 + l] : 0.0f;
    int p0 = g_rowptr[r], p1 = g_rowptr[r + 1];
    for (int p = p0; p < p1; p++) {
        int s = __ldg(&g_csrc[p]);
        float w = __ldg(&g_cw[p]);
        const float* hs = g_h3 + s * OUTF;
        a0 += w * hs[l];
        if (l < 8) a1 += w * hs[32 + l];
    }
    a0 += bias[l];
    if (l < 8) a1 += bias[32 + l];
    float m = a0;
    if (l < 8) m = fmaxf(m, a1);
    for (int off = 16; off; off >>= 1) m = fmaxf(m, __shfl_xor_sync(0xffffffffu, m, off));
    float s = expf(a0 - m) + ((l < 8) ? expf(a1 - m) : 0.0f);
    for (int off = 16; off; off >>= 1) s += __shfl_xor_sync(0xffffffffu, s, off);
    float lse = m + logf(s);
    out[r * OUTF + l] = a0 - lse;
    if (l < 8) out[r * OUTF + 32 + l] = a1 - lse;
}

// ---------------- launch ----------------
extern "C" void kernel_launch(void* const* d_in, const int* in_sizes, int n_in,
                              void* d_out, int out_size) {
    const float* x  = (const float*)d_in[0];
    const void*  ei = d_in[1];
    const float* w0 = (const float*)d_in[2];
    const float* b0 = (const float*)d_in[3];
    const float* w1 = (const float*)d_in[4];
    const float* b1 = (const float*)d_in[5];
    const float* w2 = (const float*)d_in[6];
    const float* b2 = (const float*)d_in[7];
    float* out = (float*)d_out;
    int E = in_sizes[1] / 2;

    // dropout fold-in keys: fold_in(key(42), i) = threefry((0,42), (0,i))
    unsigned fk[2][2];
    for (int i = 0; i < 2; i++) tf2x32_h(0u, 42u, 0u, (unsigned)i, fk[i][0], fk[i][1]);

    k_init<<<(NN + 255) / 256, 256>>>((const unsigned*)ei);
    k_colsum<<<dim3(2, 100), 256>>>(x);
    k_alpha<<<3, 256>>>(w0, w1, w2);
    k_packw<<<NWX + NWH + NWH, 128>>>(w0, w1, w2);
    k_count<<<(E + 255) / 256, 256>>>(ei, E);
    k_scan<<<1, 1024>>>();
    k_scatter<<<(E + 255) / 256, 256>>>(ei, E);
    k_packX<<<NN / 8, 256>>>(x);

    k_gemm1<<<NN / 8, dim3(128, 8)>>>();
    k_agg_pack<<<NN / 8, 256>>>(b0, fk[0][0], fk[0][1]);
    k_gemm2<<<NN / 8, dim3(128, 8)>>>();
    k_agg_pack<<<NN / 8, 256>>>(b1, fk[1][0], fk[1][1]);
    k_gemm3<<<NN / 16, dim3(40, 16)>>>();
    k_agg_final<<<NN / 8, 256>>>(b2, out);
}

// round 6
// speedup vs baseline: 1.1938x; 1.1938x over previous
#include <cuda_runtime.h>
#include <cstdint>

// ---------------- problem constants ----------------
#define NN    50000
#define INF   512
#define HID   128
#define OUTF  40
#define EE    600000
#define NWX   16      // INF/32 words per row
#define NWH   4       // HID/32 words per row

// ---------------- device scratch ----------------
__device__ float    g_colsum[INF];
__device__ float    g_alpha[3];         // mean(|w|) per layer
__device__ uint2    g_Xsv[NN * NWX];    // layer-0 activations (sign, valid)
__device__ uint2    g_w0sv[NWX * HID];
__device__ uint2    g_w1sv[NWH * HID];
__device__ uint2    g_w2sv[NWH * OUTF];
__device__ int      g_count[NN];
__device__ int      g_rowptr[NN + 1];
__device__ int      g_cursor[NN];
__device__ int      g_bsum[64];
__device__ float    g_dinv[NN];
__device__ int2     g_adj[EE];          // {src, w_bits}
__device__ short    g_hk[NN * HID];     // GEMM output k = 2*pos - tot (exact int)
__device__ short    g_h3k[NN * OUTF];
__device__ uint2    g_Ssv[NN * NWH];    // hidden activations (sign, valid)
__device__ int      g_is64;

// ---------------- threefry2x32 (jax-compatible) ----------------
__device__ __forceinline__ void tf2x32_d(unsigned k0, unsigned k1, unsigned c0, unsigned c1,
                                         unsigned& o0, unsigned& o1) {
    unsigned ks2 = k0 ^ k1 ^ 0x1BD11BDAu;
    unsigned x0 = c0 + k0, x1 = c1 + k1;
#define TFR_(r) { x0 += x1; x1 = __funnelshift_l(x1, x1, r); x1 ^= x0; }
    TFR_(13) TFR_(15) TFR_(26) TFR_(6)  x0 += k1;  x1 += ks2 + 1u;
    TFR_(17) TFR_(29) TFR_(16) TFR_(24) x0 += ks2; x1 += k0 + 2u;
    TFR_(13) TFR_(15) TFR_(26) TFR_(6)  x0 += k0;  x1 += k1 + 3u;
    TFR_(17) TFR_(29) TFR_(16) TFR_(24) x0 += k1;  x1 += ks2 + 4u;
    TFR_(13) TFR_(15) TFR_(26) TFR_(6)  x0 += ks2; x1 += k0 + 5u;
#undef TFR_
    o0 = x0; o1 = x1;
}

static void tf2x32_h(unsigned k0, unsigned k1, unsigned c0, unsigned c1,
                     unsigned& o0, unsigned& o1) {
    unsigned ks2 = k0 ^ k1 ^ 0x1BD11BDAu;
    unsigned x0 = c0 + k0, x1 = c1 + k1;
#define TFRH(r) { x0 += x1; x1 = (x1 << r) | (x1 >> (32 - r)); x1 ^= x0; }
    TFRH(13) TFRH(15) TFRH(26) TFRH(6)  x0 += k1;  x1 += ks2 + 1u;
    TFRH(17) TFRH(29) TFRH(16) TFRH(24) x0 += ks2; x1 += k0 + 2u;
    TFRH(13) TFRH(15) TFRH(26) TFRH(6)  x0 += k0;  x1 += k1 + 3u;
    TFRH(17) TFRH(29) TFRH(16) TFRH(24) x0 += k1;  x1 += ks2 + 4u;
    TFRH(13) TFRH(15) TFRH(26) TFRH(6)  x0 += ks2; x1 += k0 + 5u;
#undef TFRH
    o0 = x0; o1 = x1;
}

// ---------------- edge index access (int32/int64 detected at runtime) ----------------
__device__ __forceinline__ int edge_at(const void* p, int which, int e, int E) {
    if (g_is64) return (int)((const long long*)p)[(size_t)which * E + e];
    return ((const int*)p)[which * E + e];
}

// ---------------- setup kernels ----------------
__global__ void k_init(const unsigned* eb) {
    int i = blockIdx.x * blockDim.x + threadIdx.x;
    if (i < INF) g_colsum[i] = 0.0f;
    if (i < NN) { g_count[i] = 0; g_cursor[i] = 0; }
    if (i == 0) {
        int ok = 1;
        for (int t = 0; t < 64; t++) if (eb[2 * t + 1] != 0u) { ok = 0; break; }
        g_is64 = ok;
    }
}

// 500 blocks of 128 threads; thread sums 4 columns (float4) over 100 rows
__global__ void k_colsum(const float* __restrict__ x) {
    int c4 = threadIdx.x;                     // 128 threads * 4 cols = 512
    int r0 = blockIdx.x * 100;
    const float4* xp = (const float4*)x;
    float s0 = 0, s1 = 0, s2 = 0, s3 = 0;
    for (int r = r0; r < r0 + 100; r++) {
        float4 v = __ldg(&xp[r * (INF / 4) + c4]);
        s0 += v.x; s1 += v.y; s2 += v.z; s3 += v.w;
    }
    atomicAdd(&g_colsum[4 * c4 + 0], s0);
    atomicAdd(&g_colsum[4 * c4 + 1], s1);
    atomicAdd(&g_colsum[4 * c4 + 2], s2);
    atomicAdd(&g_colsum[4 * c4 + 3], s3);
}

__global__ void k_alpha(const float* __restrict__ w0, const float* __restrict__ w1,
                        const float* __restrict__ w2) {
    const float* p; int n;
    if (blockIdx.x == 0)      { p = w0; n = INF * HID; }
    else if (blockIdx.x == 1) { p = w1; n = HID * HID; }
    else                      { p = w2; n = HID * OUTF; }
    float s = 0.0f;
    for (int i = threadIdx.x; i < n; i += 256) s += fabsf(p[i]);
    __shared__ float sh[8];
    for (int off = 16; off; off >>= 1) s += __shfl_xor_sync(0xffffffffu, s, off);
    if ((threadIdx.x & 31) == 0) sh[threadIdx.x >> 5] = s;
    __syncthreads();
    if (threadIdx.x == 0) {
        float t = 0.0f;
        for (int w = 0; w < 8; w++) t += sh[w];
        g_alpha[blockIdx.x] = t / (float)n;
    }
}

// smem-staged weight packing: coalesced tile load, padded-stride assembly
__global__ void k_packw(const float* __restrict__ w0, const float* __restrict__ w1,
                        const float* __restrict__ w2) {
    __shared__ float t[32 * 129];
    int b = blockIdx.x;
    const float* src; int cols; uint2* dst;
    if (b < NWX)              { src = w0 + b * 32 * HID;           cols = HID;  dst = g_w0sv + b * HID; }
    else if (b < NWX + NWH)   { int w = b - NWX; src = w1 + w * 32 * HID;  cols = HID;  dst = g_w1sv + w * HID; }
    else                      { int w = b - NWX - NWH; src = w2 + w * 32 * OUTF; cols = OUTF; dst = g_w2sv + w * OUTF; }
    for (int i = threadIdx.x; i < 32 * cols; i += blockDim.x)
        t[(i / cols) * 129 + (i % cols)] = src[i];
    __syncthreads();
    for (int j = threadIdx.x; j < cols; j += blockDim.x) {
        unsigned sb = 0, vb = 0;
        for (int i = 0; i < 32; i++) {
            float v = t[i * 129 + j];
            sb |= (v > 0.0f ? 1u : 0u) << i;
            vb |= (v != 0.0f ? 1u : 0u) << i;
        }
        dst[j] = make_uint2(sb, vb);
    }
}

__global__ void k_count(const void* __restrict__ ei, int E) {
    int e = blockIdx.x * blockDim.x + threadIdx.x;
    if (e < E) atomicAdd(&g_count[edge_at(ei, 0, e, E)], 1);
}

// ---- 3-phase scan of g_count -> g_rowptr (+ dinv) ----
__global__ void k_scan1() {             // grid 49, block 1024: block sums
    int i = blockIdx.x * 1024 + threadIdx.x;
    int v = (i < NN) ? g_count[i] : 0;
    if (i < NN) g_dinv[i] = rsqrtf((float)(v + 1));
    int s = v;
    for (int off = 16; off; off >>= 1) s += __shfl_xor_sync(0xffffffffu, s, off);
    __shared__ int sh[32];
    int l = threadIdx.x & 31, w = threadIdx.x >> 5;
    if (l == 0) sh[w] = s;
    __syncthreads();
    if (w == 0) {
        s = sh[l];
        for (int off = 16; off; off >>= 1) s += __shfl_xor_sync(0xffffffffu, s, off);
        if (l == 0) g_bsum[blockIdx.x] = s;
    }
}

__global__ void k_scan2() {             // 1 block, 64 threads: scan of block sums
    int tid = threadIdx.x, l = tid & 31, w = tid >> 5;
    int v = (tid < 49) ? g_bsum[tid] : 0;
    int x = v;
    for (int off = 1; off < 32; off <<= 1) {
        int t = __shfl_up_sync(0xffffffffu, x, off);
        if (l >= off) x += t;
    }
    __shared__ int ws_[2];
    if (l == 31) ws_[w] = x;
    __syncthreads();
    if (w == 1) x += ws_[0];
    g_bsum[tid] = x - v;                 // exclusive prefix
    if (tid == 48) g_rowptr[NN] = x;     // total
}

__global__ void k_scan3() {             // grid 49, block 1024: rowptr
    int i = blockIdx.x * 1024 + threadIdx.x;
    int v = (i < NN) ? g_count[i] : 0;
    int l = threadIdx.x & 31, w = threadIdx.x >> 5;
    int x = v;
    for (int off = 1; off < 32; off <<= 1) {
        int t = __shfl_up_sync(0xffffffffu, x, off);
        if (l >= off) x += t;
    }
    __shared__ int sh[32];
    if (l == 31) sh[w] = x;
    __syncthreads();
    if (w == 0) {
        int y = sh[l];
        for (int off = 1; off < 32; off <<= 1) {
            int t = __shfl_up_sync(0xffffffffu, y, off);
            if (l >= off) y += t;
        }
        sh[l] = y;
    }
    __syncthreads();
    int excl = x - v + ((w > 0) ? sh[w - 1] : 0);
    if (i < NN) g_rowptr[i] = g_bsum[blockIdx.x] + excl;
}

__global__ void k_scatter(const void* __restrict__ ei, int E) {
    int e = blockIdx.x * blockDim.x + threadIdx.x;
    if (e < E) {
        int dst = edge_at(ei, 0, e, E);
        int src = edge_at(ei, 1, e, E);
        int p = g_rowptr[dst] + atomicAdd(&g_cursor[dst], 1);
        g_adj[p] = make_int2(src, __float_as_int(g_dinv[dst] * g_dinv[src]));
    }
}

__global__ void k_packX(const float* __restrict__ x) {
    int wid = threadIdx.x >> 5, l = threadIdx.x & 31;
    int r = blockIdx.x * 8 + wid;
    const float inv_n = 1.0f / (float)NN;
    for (int w = 0; w < NWX; w++) {
        int c = w * 32 + l;
        float t = x[r * INF + c] - g_colsum[c] * inv_n;
        unsigned sb = __ballot_sync(0xffffffffu, t > 0.0f);
        unsigned vb = __ballot_sync(0xffffffffu, t != 0.0f);
        if (l == 0) g_Xsv[r * NWX + w] = make_uint2(sb, vb);
    }
}

// ---------------- bit-GEMMs: write k = 2*pos - tot as int16 ----------------
__global__ void k_gemm1() {
    __shared__ uint2 ws[NWX * HID];      // 16 KB
    int tx = threadIdx.x, ty = threadIdx.y;
    int tid = ty * 64 + tx;
    for (int i = tid; i < NWX * HID; i += 512) ws[i] = g_w0sv[i];
    int r = blockIdx.x * 8 + ty;
    uint2 a[NWX];
    const uint2* ap = g_Xsv + r * NWX;
#pragma unroll
    for (int w = 0; w < NWX; w++) a[w] = __ldg(ap + w);
    __syncthreads();
    int p1 = 0, t1 = 0, p2 = 0, t2 = 0;
#pragma unroll
    for (int w = 0; w < NWX; w++) {
        uint2 b1 = ws[w * HID + tx];
        uint2 b2 = ws[w * HID + tx + 64];
        unsigned m1 = a[w].y & b1.y;
        p1 += __popc(m1 & ~(a[w].x ^ b1.x)); t1 += __popc(m1);
        unsigned m2 = a[w].y & b2.y;
        p2 += __popc(m2 & ~(a[w].x ^ b2.x)); t2 += __popc(m2);
    }
    g_hk[r * HID + tx]      = (short)(2 * p1 - t1);
    g_hk[r * HID + tx + 64] = (short)(2 * p2 - t2);
}

__global__ void k_gemm2() {
    __shared__ uint2 ws[NWH * HID];      // 4 KB
    int tx = threadIdx.x, ty = threadIdx.y;
    int tid = ty * 64 + tx;
    if (tid < NWH * HID) ws[tid] = g_w1sv[tid];
    int r = blockIdx.x * 8 + ty;
    uint2 a[NWH];
    const uint2* ap = g_Ssv + r * NWH;
#pragma unroll
    for (int w = 0; w < NWH; w++) a[w] = __ldg(ap + w);
    __syncthreads();
    int p1 = 0, t1 = 0, p2 = 0, t2 = 0;
#pragma unroll
    for (int w = 0; w < NWH; w++) {
        uint2 b1 = ws[w * HID + tx];
        uint2 b2 = ws[w * HID + tx + 64];
        unsigned m1 = a[w].y & b1.y;
        p1 += __popc(m1 & ~(a[w].x ^ b1.x)); t1 += __popc(m1);
        unsigned m2 = a[w].y & b2.y;
        p2 += __popc(m2 & ~(a[w].x ^ b2.x)); t2 += __popc(m2);
    }
    g_hk[r * HID + tx]      = (short)(2 * p1 - t1);
    g_hk[r * HID + tx + 64] = (short)(2 * p2 - t2);
}

__global__ void k_gemm3() {
    __shared__ uint2 ws[NWH * OUTF];
    int tx = threadIdx.x, ty = threadIdx.y;   // (40, 8)
    int tid = ty * 40 + tx;
    if (tid < NWH * OUTF) ws[tid] = g_w2sv[tid];
    int r = blockIdx.x * 8 + ty;
    uint2 a[NWH];
    const uint2* ap = g_Ssv + r * NWH;
#pragma unroll
    for (int w = 0; w < NWH; w++) a[w] = __ldg(ap + w);
    __syncthreads();
    int pos = 0, tot = 0;
#pragma unroll
    for (int w = 0; w < NWH; w++) {
        uint2 b = ws[w * OUTF + tx];
        unsigned m = a[w].y & b.y;
        pos += __popc(m & ~(a[w].x ^ b.x)); tot += __popc(m);
    }
    g_h3k[r * OUTF + tx] = (short)(2 * pos - tot);
}

// ---------------- aggregate (int16 rows) + bias + dropout + sign + pack ----------------
__global__ void k_agg_pack(const float* __restrict__ bias, int layer,
                           unsigned fk0, unsigned fk1) {
    int wid = threadIdx.x >> 5, l = threadIdx.x & 31;
    int r = blockIdx.x * 8 + wid;
    float dr = g_dinv[r];
    float sw = dr * dr;
    const uint2* hrow = (const uint2*)g_hk;
    uint2 hv = __ldg(&hrow[r * 32 + l]);
    int s0 = ((int)(hv.x << 16)) >> 16, s1 = (int)hv.x >> 16;
    int s2 = ((int)(hv.y << 16)) >> 16, s3 = (int)hv.y >> 16;
    float a0 = sw * (float)s0, a1 = sw * (float)s1;
    float a2 = sw * (float)s2, a3 = sw * (float)s3;
    int p = g_rowptr[r], pe = g_rowptr[r + 1];
    int2 e;
    if (p < pe) e = __ldg(&g_adj[p]);
    while (p < pe) {
        float w = __int_as_float(e.y);
        uint2 v = __ldg(&hrow[e.x * 32 + l]);
        if (++p < pe) e = __ldg(&g_adj[p]);
        int u0 = ((int)(v.x << 16)) >> 16, u1 = (int)v.x >> 16;
        int u2 = ((int)(v.y << 16)) >> 16, u3 = (int)v.y >> 16;
        a0 += w * (float)u0; a1 += w * (float)u1;
        a2 += w * (float)u2; a3 += w * (float)u3;
    }
    float alpha = g_alpha[layer];
    float4 b4 = __ldg(&((const float4*)bias)[l]);
    float v0 = alpha * a0 + b4.x;
    float v1 = alpha * a1 + b4.y;
    float v2 = alpha * a2 + b4.z;
    float v3 = alpha * a3 + b4.w;
    unsigned base = (unsigned)(r * HID + 4 * l);
    float vv[4] = {v0, v1, v2, v3};
    unsigned sn = 0, vn = 0;
#pragma unroll
    for (int k = 0; k < 4; k++) {
        unsigned o0, o1;
        tf2x32_d(fk0, fk1, 0u, base + (unsigned)k, o0, o1);
        unsigned bits = o0 ^ o1;                       // jax partitionable path
        bool keep = ((int)bits >= 0);                  // uniform < 0.5
        if (vv[k] > 0.0f) sn |= 1u << k;
        if (keep && vv[k] != 0.0f) vn |= 1u << k;
    }
    int sh = 4 * (l & 7);
    unsigned s4 = sn << sh, v4 = vn << sh;
    s4 |= __shfl_xor_sync(0xffffffffu, s4, 1);  v4 |= __shfl_xor_sync(0xffffffffu, v4, 1);
    s4 |= __shfl_xor_sync(0xffffffffu, s4, 2);  v4 |= __shfl_xor_sync(0xffffffffu, v4, 2);
    s4 |= __shfl_xor_sync(0xffffffffu, s4, 4);  v4 |= __shfl_xor_sync(0xffffffffu, v4, 4);
    if ((l & 7) == 0) g_Ssv[r * NWH + (l >> 3)] = make_uint2(s4, v4);
}

// ---------------- final aggregate (40 int16 feats) + bias + log_softmax ----------------
__global__ void k_agg_final(const float* __restrict__ bias, float* __restrict__ out) {
    int wid = threadIdx.x >> 5, l = threadIdx.x & 31;
    int r = blockIdx.x * 8 + wid;
    float dr = g_dinv[r];
    float sw = dr * dr;
    const unsigned* hrow = (const unsigned*)g_h3k;
    bool act = (l < 20);
    float a0 = 0.0f, a1 = 0.0f;
    if (act) {
        unsigned u = __ldg(&hrow[r * 20 + l]);
        a0 = sw * (float)(((int)(u << 16)) >> 16);
        a1 = sw * (float)((int)u >> 16);
    }
    int p = g_rowptr[r], pe = g_rowptr[r + 1];
    int2 e;
    if (p < pe) e = __ldg(&g_adj[p]);
    while (p < pe) {
        float w = __int_as_float(e.y);
        unsigned u = act ? __ldg(&hrow[e.x * 20 + l]) : 0u;
        if (++p < pe) e = __ldg(&g_adj[p]);
        a0 += w * (float)(((int)(u << 16)) >> 16);
        a1 += w * (float)((int)u >> 16);
    }
    float alpha = g_alpha[2];
    float v0 = 0.0f, v1 = 0.0f;
    if (act) {
        float2 b2v = __ldg(&((const float2*)bias)[l]);
        v0 = alpha * a0 + b2v.x;
        v1 = alpha * a1 + b2v.y;
    }
    float m = act ? fmaxf(v0, v1) : -3.4e38f;
    for (int off = 16; off; off >>= 1) m = fmaxf(m, __shfl_xor_sync(0xffffffffu, m, off));
    float s = act ? (expf(v0 - m) + expf(v1 - m)) : 0.0f;
    for (int off = 16; off; off >>= 1) s += __shfl_xor_sync(0xffffffffu, s, off);
    float lse = m + logf(s);
    if (act) {
        float2 o; o.x = v0 - lse; o.y = v1 - lse;
        ((float2*)out)[r * 20 + l] = o;
    }
}

// ---------------- launch ----------------
extern "C" void kernel_launch(void* const* d_in, const int* in_sizes, int n_in,
                              void* d_out, int out_size) {
    const float* x  = (const float*)d_in[0];
    const void*  ei = d_in[1];
    const float* w0 = (const float*)d_in[2];
    const float* b0 = (const float*)d_in[3];
    const float* w1 = (const float*)d_in[4];
    const float* b1 = (const float*)d_in[5];
    const float* w2 = (const float*)d_in[6];
    const float* b2 = (const float*)d_in[7];
    float* out = (float*)d_out;
    int E = in_sizes[1] / 2;

    // dropout fold-in keys: fold_in(key(42), i) = threefry((0,42), (0,i))
    unsigned fk[2][2];
    for (int i = 0; i < 2; i++) tf2x32_h(0u, 42u, 0u, (unsigned)i, fk[i][0], fk[i][1]);

    k_init<<<(NN + 255) / 256, 256>>>((const unsigned*)ei);
    k_colsum<<<500, 128>>>(x);
    k_alpha<<<3, 256>>>(w0, w1, w2);
    k_packw<<<NWX + NWH + NWH, 256>>>(w0, w1, w2);
    k_count<<<(E + 255) / 256, 256>>>(ei, E);
    k_scan1<<<49, 1024>>>();
    k_scan2<<<1, 64>>>();
    k_scan3<<<49, 1024>>>();
    k_scatter<<<(E + 255) / 256, 256>>>(ei, E);
    k_packX<<<NN / 8, 256>>>(x);

    k_gemm1<<<NN / 8, dim3(64, 8)>>>();
    k_agg_pack<<<NN / 8, 256>>>(b0, 0, fk[0][0], fk[0][1]);
    k_gemm2<<<NN / 8, dim3(64, 8)>>>();
    k_agg_pack<<<NN / 8, 256>>>(b1, 1, fk[1][0], fk[1][1]);
    k_gemm3<<<NN / 8, dim3(40, 8)>>>();
    k_agg_final<<<NN / 8, 256>>>(b2, out);
}

// round 7
// speedup vs baseline: 1.2769x; 1.0696x over previous
#include <cuda_runtime.h>
#include <cstdint>

// ---------------- problem constants ----------------
#define NN    50000
#define INF   512
#define HID   128
#define OUTF  40
#define EE    600000
#define NWX   16      // INF/32 words per row
#define NWH   4       // HID/32 words per row

// ---------------- device scratch ----------------
__device__ float    g_colsum[INF];
__device__ float    g_araw[3];          // sum(|w|) per layer (atomic-accumulated)
__device__ int      g_wall[3];          // 1 if ALL weight bits valid (no exact zeros)
__device__ __align__(16) uint2    g_Xsv[NN * NWX];    // layer-0 activations (sign, valid)
__device__ __align__(16) unsigned g_w0s[NWX * HID];   // weight sign words (pair-readable)
__device__ __align__(16) unsigned g_w0v[NWX * HID];   // weight valid words (slow path only)
__device__ __align__(16) unsigned g_w1s[NWH * HID];
__device__ __align__(16) unsigned g_w1v[NWH * HID];
__device__ __align__(16) unsigned g_w2s[NWH * OUTF];
__device__ __align__(16) unsigned g_w2v[NWH * OUTF];
__device__ int      g_count[NN];
__device__ int      g_rowptr[NN + 1];
__device__ int      g_cursor[NN];
__device__ int      g_bsum[64];
__device__ float    g_dinv[NN];
__device__ __align__(16) int2  g_adj[EE];            // {src, w_bits}
__device__ __align__(16) short g_hk[NN * HID];       // GEMM output k (exact int)
__device__ __align__(16) short g_h3k[NN * OUTF];
__device__ __align__(16) uint2 g_Ssv[NN * NWH];      // hidden activations (sign, valid)
__device__ int      g_rt[NN];          // per-row sum popc(valid) for current layer input
__device__ int      g_is64;

// ---------------- threefry2x32 (jax-compatible) ----------------
__device__ __forceinline__ void tf2x32_d(unsigned k0, unsigned k1, unsigned c0, unsigned c1,
                                         unsigned& o0, unsigned& o1) {
    unsigned ks2 = k0 ^ k1 ^ 0x1BD11BDAu;
    unsigned x0 = c0 + k0, x1 = c1 + k1;
#define TFR_(r) { x0 += x1; x1 = __funnelshift_l(x1, x1, r); x1 ^= x0; }
    TFR_(13) TFR_(15) TFR_(26) TFR_(6)  x0 += k1;  x1 += ks2 + 1u;
    TFR_(17) TFR_(29) TFR_(16) TFR_(24) x0 += ks2; x1 += k0 + 2u;
    TFR_(13) TFR_(15) TFR_(26) TFR_(6)  x0 += k0;  x1 += k1 + 3u;
    TFR_(17) TFR_(29) TFR_(16) TFR_(24) x0 += k1;  x1 += ks2 + 4u;
    TFR_(13) TFR_(15) TFR_(26) TFR_(6)  x0 += ks2; x1 += k0 + 5u;
#undef TFR_
    o0 = x0; o1 = x1;
}

static void tf2x32_h(unsigned k0, unsigned k1, unsigned c0, unsigned c1,
                     unsigned& o0, unsigned& o1) {
    unsigned ks2 = k0 ^ k1 ^ 0x1BD11BDAu;
    unsigned x0 = c0 + k0, x1 = c1 + k1;
#define TFRH(r) { x0 += x1; x1 = (x1 << r) | (x1 >> (32 - r)); x1 ^= x0; }
    TFRH(13) TFRH(15) TFRH(26) TFRH(6)  x0 += k1;  x1 += ks2 + 1u;
    TFRH(17) TFRH(29) TFRH(16) TFRH(24) x0 += ks2; x1 += k0 + 2u;
    TFRH(13) TFRH(15) TFRH(26) TFRH(6)  x0 += k0;  x1 += k1 + 3u;
    TFRH(17) TFRH(29) TFRH(16) TFRH(24) x0 += k1;  x1 += ks2 + 4u;
    TFRH(13) TFRH(15) TFRH(26) TFRH(6)  x0 += ks2; x1 += k0 + 5u;
#undef TFRH
    o0 = x0; o1 = x1;
}

// ---------------- edge index access (int32/int64 detected at runtime) ----------------
__device__ __forceinline__ int edge_at(const void* p, int which, int e, int E) {
    if (g_is64) return (int)((const long long*)p)[(size_t)which * E + e];
    return ((const int*)p)[which * E + e];
}

// ---------------- setup kernels ----------------
__global__ void k_init(const unsigned* eb) {
    int i = blockIdx.x * blockDim.x + threadIdx.x;
    if (i < INF) g_colsum[i] = 0.0f;
    if (i < 3)  { g_araw[i] = 0.0f; g_wall[i] = 1; }
    if (i < NN) { g_count[i] = 0; g_cursor[i] = 0; }
    if (i == 0) {
        int ok = 1;
        for (int t = 0; t < 64; t++) if (eb[2 * t + 1] != 0u) { ok = 0; break; }
        g_is64 = ok;
    }
}

// 500 blocks of 128 threads; thread sums 4 columns (float4) over 100 rows
__global__ void k_colsum(const float* __restrict__ x) {
    int c4 = threadIdx.x;
    int r0 = blockIdx.x * 100;
    const float4* xp = (const float4*)x;
    float s0 = 0, s1 = 0, s2 = 0, s3 = 0;
    for (int r = r0; r < r0 + 100; r++) {
        float4 v = __ldg(&xp[r * (INF / 4) + c4]);
        s0 += v.x; s1 += v.y; s2 += v.z; s3 += v.w;
    }
    atomicAdd(&g_colsum[4 * c4 + 0], s0);
    atomicAdd(&g_colsum[4 * c4 + 1], s1);
    atomicAdd(&g_colsum[4 * c4 + 2], s2);
    atomicAdd(&g_colsum[4 * c4 + 3], s3);
}

// thread-per-output-word packing; also accumulates sum|w| and valid-all flags
__global__ void k_packw(const float* __restrict__ w0, const float* __restrict__ w1,
                        const float* __restrict__ w2) {
    int t = blockIdx.x * 256 + threadIdx.x;
    if (t >= NWX * HID + NWH * HID + NWH * OUTF) return;
    const float* src; int stride, w, j, L; unsigned *ds, *dv;
    if (t < NWX * HID) {
        L = 0; w = t >> 7; j = t & 127; src = w0; stride = HID; ds = g_w0s; dv = g_w0v;
    } else if (t < NWX * HID + NWH * HID) {
        int u = t - NWX * HID;
        L = 1; w = u >> 7; j = u & 127; src = w1; stride = HID; ds = g_w1s; dv = g_w1v;
    } else {
        int u = t - NWX * HID - NWH * HID;
        L = 2; w = u / OUTF; j = u % OUTF; src = w2; stride = OUTF; ds = g_w2s; dv = g_w2v;
    }
    unsigned sb = 0, vb = 0;
    float asum = 0.0f;
#pragma unroll 8
    for (int i = 0; i < 32; i++) {
        float v = __ldg(&src[(w * 32 + i) * stride + j]);
        sb |= (v > 0.0f ? 1u : 0u) << i;
        vb |= (v != 0.0f ? 1u : 0u) << i;
        asum += fabsf(v);
    }
    ds[w * stride + j] = sb;
    dv[w * stride + j] = vb;
    atomicAdd(&g_araw[L], asum);
    if (vb != 0xffffffffu) g_wall[L] = 0;
}

__global__ void k_count(const void* __restrict__ ei, int E) {
    int e = blockIdx.x * blockDim.x + threadIdx.x;
    if (e < E) atomicAdd(&g_count[edge_at(ei, 0, e, E)], 1);
}

// ---- 3-phase scan of g_count -> g_rowptr (+ dinv) ----
__global__ void k_scan1() {
    int i = blockIdx.x * 1024 + threadIdx.x;
    int v = (i < NN) ? g_count[i] : 0;
    if (i < NN) g_dinv[i] = rsqrtf((float)(v + 1));
    int s = v;
    for (int off = 16; off; off >>= 1) s += __shfl_xor_sync(0xffffffffu, s, off);
    __shared__ int sh[32];
    int l = threadIdx.x & 31, w = threadIdx.x >> 5;
    if (l == 0) sh[w] = s;
    __syncthreads();
    if (w == 0) {
        s = sh[l];
        for (int off = 16; off; off >>= 1) s += __shfl_xor_sync(0xffffffffu, s, off);
        if (l == 0) g_bsum[blockIdx.x] = s;
    }
}

__global__ void k_scan2() {
    int tid = threadIdx.x, l = tid & 31, w = tid >> 5;
    int v = (tid < 49) ? g_bsum[tid] : 0;
    int x = v;
    for (int off = 1; off < 32; off <<= 1) {
        int t = __shfl_up_sync(0xffffffffu, x, off);
        if (l >= off) x += t;
    }
    __shared__ int ws_[2];
    if (l == 31) ws_[w] = x;
    __syncthreads();
    if (w == 1) x += ws_[0];
    g_bsum[tid] = x - v;
    if (tid == 48) g_rowptr[NN] = x;
}

__global__ void k_scan3() {
    int i = blockIdx.x * 1024 + threadIdx.x;
    int v = (i < NN) ? g_count[i] : 0;
    int l = threadIdx.x & 31, w = threadIdx.x >> 5;
    int x = v;
    for (int off = 1; off < 32; off <<= 1) {
        int t = __shfl_up_sync(0xffffffffu, x, off);
        if (l >= off) x += t;
    }
    __shared__ int sh[32];
    if (l == 31) sh[w] = x;
    __syncthreads();
    if (w == 0) {
        int y = sh[l];
        for (int off = 1; off < 32; off <<= 1) {
            int t = __shfl_up_sync(0xffffffffu, y, off);
            if (l >= off) y += t;
        }
        sh[l] = y;
    }
    __syncthreads();
    int excl = x - v + ((w > 0) ? sh[w - 1] : 0);
    if (i < NN) g_rowptr[i] = g_bsum[blockIdx.x] + excl;
}

__global__ void k_scatter(const void* __restrict__ ei, int E) {
    int e = blockIdx.x * blockDim.x + threadIdx.x;
    if (e < E) {
        int dst = edge_at(ei, 0, e, E);
        int src = edge_at(ei, 1, e, E);
        int p = g_rowptr[dst] + atomicAdd(&g_cursor[dst], 1);
        g_adj[p] = make_int2(src, __float_as_int(g_dinv[dst] * g_dinv[src]));
    }
}

__global__ void k_packX(const float* __restrict__ x) {
    int wid = threadIdx.x >> 5, l = threadIdx.x & 31;
    int r = blockIdx.x * 8 + wid;
    const float inv_n = 1.0f / (float)NN;
    int tot = 0;
    for (int w = 0; w < NWX; w++) {
        int c = w * 32 + l;
        float t = x[r * INF + c] - g_colsum[c] * inv_n;
        unsigned sb = __ballot_sync(0xffffffffu, t > 0.0f);
        unsigned vb = __ballot_sync(0xffffffffu, t != 0.0f);
        if (l == 0) { g_Xsv[r * NWX + w] = make_uint2(sb, vb); tot += __popc(vb); }
    }
    if (l == 0) g_rt[r] = tot;
}

// ---------------- bit-GEMMs (fast path: 1 LOP3 + POPC + IADD per word-MAC) ----------------
__global__ void k_gemm1() {
    __shared__ uint2 ws2[NWX * 64];      // sign pairs: 8 KB
    __shared__ uint2 wv2[NWX * 64];      // valid pairs (slow path only)
    int tx = threadIdx.x, ty = threadIdx.y;
    int tid = ty * 64 + tx;
    int wall = g_wall[0];
    {
        unsigned* u = (unsigned*)ws2;
        for (int i = tid; i < NWX * HID; i += 512) u[i] = g_w0s[i];
        if (!wall) {
            unsigned* v = (unsigned*)wv2;
            for (int i = tid; i < NWX * HID; i += 512) v[i] = g_w0v[i];
        }
    }
    int r = blockIdx.x * 8 + ty;
    uint2 a[NWX];
    const uint2* ap = g_Xsv + r * NWX;
#pragma unroll
    for (int w = 0; w < NWX; w++) a[w] = __ldg(ap + w);
    int rt = g_rt[r];
    __syncthreads();
    int k0, k1;
    if (wall) {
        int p0 = 0, p1 = 0;
#pragma unroll
        for (int w = 0; w < NWX; w++) {
            uint2 b = ws2[w * 64 + tx];
            p0 += __popc(a[w].y & ~(a[w].x ^ b.x));
            p1 += __popc(a[w].y & ~(a[w].x ^ b.y));
        }
        k0 = 2 * p0 - rt; k1 = 2 * p1 - rt;
    } else {
        int p0 = 0, t0 = 0, p1 = 0, t1 = 0;
#pragma unroll
        for (int w = 0; w < NWX; w++) {
            uint2 b = ws2[w * 64 + tx];
            uint2 v = wv2[w * 64 + tx];
            unsigned m0 = a[w].y & v.x;
            p0 += __popc(m0 & ~(a[w].x ^ b.x)); t0 += __popc(m0);
            unsigned m1 = a[w].y & v.y;
            p1 += __popc(m1 & ~(a[w].x ^ b.y)); t1 += __popc(m1);
        }
        k0 = 2 * p0 - t0; k1 = 2 * p1 - t1;
    }
    ((unsigned*)g_hk)[r * 64 + tx] =
        (unsigned)(unsigned short)k0 | ((unsigned)(unsigned short)k1 << 16);
}

__global__ void k_gemm2() {
    __shared__ uint2 ws2[NWH * 64];
    __shared__ uint2 wv2[NWH * 64];
    int tx = threadIdx.x, ty = threadIdx.y;
    int tid = ty * 64 + tx;
    int wall = g_wall[1];
    if (tid < NWH * HID) {
        ((unsigned*)ws2)[tid] = g_w1s[tid];
        if (!wall) ((unsigned*)wv2)[tid] = g_w1v[tid];
    }
    int r = blockIdx.x * 8 + ty;
    uint2 a[NWH];
    const uint2* ap = g_Ssv + r * NWH;
#pragma unroll
    for (int w = 0; w < NWH; w++) a[w] = __ldg(ap + w);
    int rt = g_rt[r];
    __syncthreads();
    int k0, k1;
    if (wall) {
        int p0 = 0, p1 = 0;
#pragma unroll
        for (int w = 0; w < NWH; w++) {
            uint2 b = ws2[w * 64 + tx];
            p0 += __popc(a[w].y & ~(a[w].x ^ b.x));
            p1 += __popc(a[w].y & ~(a[w].x ^ b.y));
        }
        k0 = 2 * p0 - rt; k1 = 2 * p1 - rt;
    } else {
        int p0 = 0, t0 = 0, p1 = 0, t1 = 0;
#pragma unroll
        for (int w = 0; w < NWH; w++) {
            uint2 b = ws2[w * 64 + tx];
            uint2 v = wv2[w * 64 + tx];
            unsigned m0 = a[w].y & v.x;
            p0 += __popc(m0 & ~(a[w].x ^ b.x)); t0 += __popc(m0);
            unsigned m1 = a[w].y & v.y;
            p1 += __popc(m1 & ~(a[w].x ^ b.y)); t1 += __popc(m1);
        }
        k0 = 2 * p0 - t0; k1 = 2 * p1 - t1;
    }
    ((unsigned*)g_hk)[r * 64 + tx] =
        (unsigned)(unsigned short)k0 | ((unsigned)(unsigned short)k1 << 16);
}

__global__ void k_gemm3() {
    __shared__ uint2 ws2[NWH * 20];
    __shared__ uint2 wv2[NWH * 20];
    int tx = threadIdx.x, ty = threadIdx.y;   // (20, 16)
    int tid = ty * 20 + tx;
    int wall = g_wall[2];
    if (tid < NWH * OUTF) {
        ((unsigned*)ws2)[tid] = g_w2s[tid];
        if (!wall) ((unsigned*)wv2)[tid] = g_w2v[tid];
    }
    int r = blockIdx.x * 16 + ty;
    uint2 a[NWH];
    const uint2* ap = g_Ssv + r * NWH;
#pragma unroll
    for (int w = 0; w < NWH; w++) a[w] = __ldg(ap + w);
    int rt = g_rt[r];
    __syncthreads();
    int k0, k1;
    if (wall) {
        int p0 = 0, p1 = 0;
#pragma unroll
        for (int w = 0; w < NWH; w++) {
            uint2 b = ws2[w * 20 + tx];
            p0 += __popc(a[w].y & ~(a[w].x ^ b.x));
            p1 += __popc(a[w].y & ~(a[w].x ^ b.y));
        }
        k0 = 2 * p0 - rt; k1 = 2 * p1 - rt;
    } else {
        int p0 = 0, t0 = 0, p1 = 0, t1 = 0;
#pragma unroll
        for (int w = 0; w < NWH; w++) {
            uint2 b = ws2[w * 20 + tx];
            uint2 v = wv2[w * 20 + tx];
            unsigned m0 = a[w].y & v.x;
            p0 += __popc(m0 & ~(a[w].x ^ b.x)); t0 += __popc(m0);
            unsigned m1 = a[w].y & v.y;
            p1 += __popc(m1 & ~(a[w].x ^ b.y)); t1 += __popc(m1);
        }
        k0 = 2 * p0 - t0; k1 = 2 * p1 - t1;
    }
    ((unsigned*)g_h3k)[r * 20 + tx] =
        (unsigned)(unsigned short)k0 | ((unsigned)(unsigned short)k1 << 16);
}

// ---------------- aggregate (int16 rows) + bias + dropout + sign + pack + rowtot ----------------
__global__ void k_agg_pack(const float* __restrict__ bias, int layer, float inv_n,
                           unsigned fk0, unsigned fk1) {
    int wid = threadIdx.x >> 5, l = threadIdx.x & 31;
    int r = blockIdx.x * 8 + wid;
    float dr = g_dinv[r];
    float sw = dr * dr;
    const uint2* hrow = (const uint2*)g_hk;
    uint2 hv = __ldg(&hrow[r * 32 + l]);
    int s0 = ((int)(hv.x << 16)) >> 16, s1 = (int)hv.x >> 16;
    int s2 = ((int)(hv.y << 16)) >> 16, s3 = (int)hv.y >> 16;
    float a0 = sw * (float)s0, a1 = sw * (float)s1;
    float a2 = sw * (float)s2, a3 = sw * (float)s3;
    int p = g_rowptr[r], pe = g_rowptr[r + 1];
    int2 e;
    if (p < pe) e = __ldg(&g_adj[p]);
    while (p < pe) {
        float w = __int_as_float(e.y);
        uint2 v = __ldg(&hrow[e.x * 32 + l]);
        if (++p < pe) e = __ldg(&g_adj[p]);
        int u0 = ((int)(v.x << 16)) >> 16, u1 = (int)v.x >> 16;
        int u2 = ((int)(v.y << 16)) >> 16, u3 = (int)v.y >> 16;
        a0 += w * (float)u0; a1 += w * (float)u1;
        a2 += w * (float)u2; a3 += w * (float)u3;
    }
    float alpha = g_araw[layer] * inv_n;
    float4 b4 = __ldg(&((const float4*)bias)[l]);
    float vv[4];
    vv[0] = alpha * a0 + b4.x;
    vv[1] = alpha * a1 + b4.y;
    vv[2] = alpha * a2 + b4.z;
    vv[3] = alpha * a3 + b4.w;
    unsigned base = (unsigned)(r * HID + 4 * l);
    unsigned sn = 0, vn = 0;
#pragma unroll
    for (int k = 0; k < 4; k++) {
        unsigned o0, o1;
        tf2x32_d(fk0, fk1, 0u, base + (unsigned)k, o0, o1);
        unsigned bits = o0 ^ o1;                       // jax partitionable path
        bool keep = ((int)bits >= 0);                  // uniform < 0.5
        if (vv[k] > 0.0f) sn |= 1u << k;
        if (keep && vv[k] != 0.0f) vn |= 1u << k;
    }
    int sh = 4 * (l & 7);
    unsigned s4 = sn << sh, v4 = vn << sh;
    s4 |= __shfl_xor_sync(0xffffffffu, s4, 1);  v4 |= __shfl_xor_sync(0xffffffffu, v4, 1);
    s4 |= __shfl_xor_sync(0xffffffffu, s4, 2);  v4 |= __shfl_xor_sync(0xffffffffu, v4, 2);
    s4 |= __shfl_xor_sync(0xffffffffu, s4, 4);  v4 |= __shfl_xor_sync(0xffffffffu, v4, 4);
    int t = ((l & 7) == 0) ? __popc(v4) : 0;
    t += __shfl_xor_sync(0xffffffffu, t, 8);
    t += __shfl_xor_sync(0xffffffffu, t, 16);
    if ((l & 7) == 0) g_Ssv[r * NWH + (l >> 3)] = make_uint2(s4, v4);
    if (l == 0) g_rt[r] = t;
}

// ---------------- final aggregate (40 int16 feats) + bias + log_softmax ----------------
__global__ void k_agg_final(const float* __restrict__ bias, float* __restrict__ out) {
    int wid = threadIdx.x >> 5, l = threadIdx.x & 31;
    int r = blockIdx.x * 8 + wid;
    float dr = g_dinv[r];
    float sw = dr * dr;
    const unsigned* hrow = (const unsigned*)g_h3k;
    bool act = (l < 20);
    float a0 = 0.0f, a1 = 0.0f;
    if (act) {
        unsigned u = __ldg(&hrow[r * 20 + l]);
        a0 = sw * (float)(((int)(u << 16)) >> 16);
        a1 = sw * (float)((int)u >> 16);
    }
    int p = g_rowptr[r], pe = g_rowptr[r + 1];
    int2 e;
    if (p < pe) e = __ldg(&g_adj[p]);
    while (p < pe) {
        float w = __int_as_float(e.y);
        unsigned u = act ? __ldg(&hrow[e.x * 20 + l]) : 0u;
        if (++p < pe) e = __ldg(&g_adj[p]);
        a0 += w * (float)(((int)(u << 16)) >> 16);
        a1 += w * (float)((int)u >> 16);
    }
    float alpha = g_araw[2] * (1.0f / (float)(HID * OUTF));
    float v0 = 0.0f, v1 = 0.0f;
    if (act) {
        float2 b2v = __ldg(&((const float2*)bias)[l]);
        v0 = alpha * a0 + b2v.x;
        v1 = alpha * a1 + b2v.y;
    }
    float m = act ? fmaxf(v0, v1) : -3.4e38f;
    for (int off = 16; off; off >>= 1) m = fmaxf(m, __shfl_xor_sync(0xffffffffu, m, off));
    float s = act ? (expf(v0 - m) + expf(v1 - m)) : 0.0f;
    for (int off = 16; off; off >>= 1) s += __shfl_xor_sync(0xffffffffu, s, off);
    float lse = m + logf(s);
    if (act) {
        float2 o; o.x = v0 - lse; o.y = v1 - lse;
        ((float2*)out)[r * 20 + l] = o;
    }
}

// ---------------- launch ----------------
extern "C" void kernel_launch(void* const* d_in, const int* in_sizes, int n_in,
                              void* d_out, int out_size) {
    const float* x  = (const float*)d_in[0];
    const void*  ei = d_in[1];
    const float* w0 = (const float*)d_in[2];
    const float* b0 = (const float*)d_in[3];
    const float* w1 = (const float*)d_in[4];
    const float* b1 = (const float*)d_in[5];
    const float* w2 = (const float*)d_in[6];
    const float* b2 = (const float*)d_in[7];
    float* out = (float*)d_out;
    int E = in_sizes[1] / 2;

    // dropout fold-in keys: fold_in(key(42), i) = threefry((0,42), (0,i))
    unsigned fk[2][2];
    for (int i = 0; i < 2; i++) tf2x32_h(0u, 42u, 0u, (unsigned)i, fk[i][0], fk[i][1]);

    k_init<<<(NN + 255) / 256, 256>>>((const unsigned*)ei);
    k_colsum<<<500, 128>>>(x);
    k_packw<<<11, 256>>>(w0, w1, w2);
    k_count<<<(E + 255) / 256, 256>>>(ei, E);
    k_scan1<<<49, 1024>>>();
    k_scan2<<<1, 64>>>();
    k_scan3<<<49, 1024>>>();
    k_scatter<<<(E + 255) / 256, 256>>>(ei, E);
    k_packX<<<NN / 8, 256>>>(x);

    k_gemm1<<<NN / 8, dim3(64, 8)>>>();
    k_agg_pack<<<NN / 8, 256>>>(b0, 0, 1.0f / (float)(INF * HID), fk[0][0], fk[0][1]);
    k_gemm2<<<NN / 8, dim3(64, 8)>>>();
    k_agg_pack<<<NN / 8, 256>>>(b1, 1, 1.0f / (float)(HID * HID), fk[1][0], fk[1][1]);
    k_gemm3<<<NN / 16, dim3(20, 16)>>>();
    k_agg_final<<<NN / 8, 256>>>(b2, out);
}

// round 8
// speedup vs baseline: 1.6539x; 1.2953x over previous
#include <cuda_runtime.h>
#include <cstdint>

// ---------------- problem constants ----------------
#define NN    50000
#define INF   512
#define HID   128
#define OUTF  40
#define NWX   16      // INF/32 words per row
#define NWH   4       // HID/32 words per row
#define EE    600000
#define NPACKW (NWX*HID + NWH*HID + NWH*OUTF)   // 2720

// ---------------- device scratch ----------------
__device__ float    g_colsum[INF];
__device__ float    g_araw[3];          // sum(|w|) per layer
__device__ int      g_wall[3];          // 1 if ALL weight bits valid
__device__ __align__(16) unsigned g_w0s[NWX * HID];
__device__ __align__(16) unsigned g_w0v[NWX * HID];
__device__ __align__(16) unsigned g_w1s[NWH * HID];
__device__ __align__(16) unsigned g_w1v[NWH * HID];
__device__ __align__(16) unsigned g_w2s[NWH * OUTF];
__device__ __align__(16) unsigned g_w2v[NWH * OUTF];
__device__ int      g_count[NN];
__device__ int      g_rowptr[NN + 1];
__device__ int      g_bsum[64];
__device__ float    g_dinv[NN];
__device__ __align__(16) int2  g_adj[EE];       // {src, w_bits}
__device__ __align__(16) short g_hk[NN * HID];  // layer0 GEMM out (exact int16)
__device__ __align__(16) short g_hkB[NN * HID]; // layer1 GEMM out
__device__ __align__(16) short g_h3k[NN * OUTF];
__device__ int      g_is64;

// ---------------- threefry2x32 (jax-compatible) ----------------
__device__ __forceinline__ void tf2x32_d(unsigned k0, unsigned k1, unsigned c0, unsigned c1,
                                         unsigned& o0, unsigned& o1) {
    unsigned ks2 = k0 ^ k1 ^ 0x1BD11BDAu;
    unsigned x0 = c0 + k0, x1 = c1 + k1;
#define TFR_(r) { x0 += x1; x1 = __funnelshift_l(x1, x1, r); x1 ^= x0; }
    TFR_(13) TFR_(15) TFR_(26) TFR_(6)  x0 += k1;  x1 += ks2 + 1u;
    TFR_(17) TFR_(29) TFR_(16) TFR_(24) x0 += ks2; x1 += k0 + 2u;
    TFR_(13) TFR_(15) TFR_(26) TFR_(6)  x0 += k0;  x1 += k1 + 3u;
    TFR_(17) TFR_(29) TFR_(16) TFR_(24) x0 += k1;  x1 += ks2 + 4u;
    TFR_(13) TFR_(15) TFR_(26) TFR_(6)  x0 += ks2; x1 += k0 + 5u;
#undef TFR_
    o0 = x0; o1 = x1;
}

static void tf2x32_h(unsigned k0, unsigned k1, unsigned c0, unsigned c1,
                     unsigned& o0, unsigned& o1) {
    unsigned ks2 = k0 ^ k1 ^ 0x1BD11BDAu;
    unsigned x0 = c0 + k0, x1 = c1 + k1;
#define TFRH(r) { x0 += x1; x1 = (x1 << r) | (x1 >> (32 - r)); x1 ^= x0; }
    TFRH(13) TFRH(15) TFRH(26) TFRH(6)  x0 += k1;  x1 += ks2 + 1u;
    TFRH(17) TFRH(29) TFRH(16) TFRH(24) x0 += ks2; x1 += k0 + 2u;
    TFRH(13) TFRH(15) TFRH(26) TFRH(6)  x0 += k0;  x1 += k1 + 3u;
    TFRH(17) TFRH(29) TFRH(16) TFRH(24) x0 += k1;  x1 += ks2 + 4u;
    TFRH(13) TFRH(15) TFRH(26) TFRH(6)  x0 += ks2; x1 += k0 + 5u;
#undef TFRH
    o0 = x0; o1 = x1;
}

__device__ __forceinline__ int edge_at(const void* p, int which, int e, int E) {
    if (g_is64) return (int)((const long long*)p)[(size_t)which * E + e];
    return ((const int*)p)[which * E + e];
}

// ---------------- k_init ----------------
__global__ void k_init(const unsigned* eb) {
    int i = blockIdx.x * blockDim.x + threadIdx.x;
    if (i < INF) g_colsum[i] = 0.0f;
    if (i < 3)  { g_araw[i] = 0.0f; g_wall[i] = 1; }
    if (i < NN) g_count[i] = 0;
    if (i == 0) {
        int ok = 1;
        for (int t = 0; t < 64; t++) if (eb[2 * t + 1] != 0u) { ok = 0; break; }
        g_is64 = ok;
    }
}

// ---------------- k_pre: colsum (250) | packw (11) | count (rest) ----------------
__global__ void k_pre(const float* __restrict__ x,
                      const float* __restrict__ w0, const float* __restrict__ w1,
                      const float* __restrict__ w2,
                      const void* __restrict__ ei, int E) {
    int b = blockIdx.x, tid = threadIdx.x;
    if (b < 250) {                       // ---- colsum: 200 rows per block
        int c4 = tid & 127;
        int r0 = b * 200 + (tid >> 7) * 100;
        const float4* xp = (const float4*)x;
        float s0 = 0, s1 = 0, s2 = 0, s3 = 0;
        for (int r = r0; r < r0 + 100; r++) {
            float4 v = __ldg(&xp[r * (INF / 4) + c4]);
            s0 += v.x; s1 += v.y; s2 += v.z; s3 += v.w;
        }
        atomicAdd(&g_colsum[4 * c4 + 0], s0);
        atomicAdd(&g_colsum[4 * c4 + 1], s1);
        atomicAdd(&g_colsum[4 * c4 + 2], s2);
        atomicAdd(&g_colsum[4 * c4 + 3], s3);
    } else if (b < 261) {                // ---- packw
        int t = (b - 250) * 256 + tid;
        if (t >= NPACKW) return;
        const float* src; int stride, w, j, L; unsigned *ds, *dv;
        if (t < NWX * HID) {
            L = 0; w = t >> 7; j = t & 127; src = w0; stride = HID; ds = g_w0s; dv = g_w0v;
        } else if (t < NWX * HID + NWH * HID) {
            int u = t - NWX * HID;
            L = 1; w = u >> 7; j = u & 127; src = w1; stride = HID; ds = g_w1s; dv = g_w1v;
        } else {
            int u = t - NWX * HID - NWH * HID;
            L = 2; w = u / OUTF; j = u % OUTF; src = w2; stride = OUTF; ds = g_w2s; dv = g_w2v;
        }
        unsigned sb = 0, vb = 0;
        float asum = 0.0f;
#pragma unroll 8
        for (int i = 0; i < 32; i++) {
            float v = __ldg(&src[(w * 32 + i) * stride + j]);
            sb |= (v > 0.0f ? 1u : 0u) << i;
            vb |= (v != 0.0f ? 1u : 0u) << i;
            asum += fabsf(v);
        }
        ds[w * stride + j] = sb;
        dv[w * stride + j] = vb;
        atomicAdd(&g_araw[L], asum);
        if (vb != 0xffffffffu) g_wall[L] = 0;
    } else {                             // ---- degree count
        int e = (b - 261) * 256 + tid;
        if (e < E) atomicAdd(&g_count[edge_at(ei, 0, e, E)], 1);
    }
}

// ---- 3-phase scan of g_count -> g_rowptr (+ dinv) ----
__global__ void k_scan1() {
    int i = blockIdx.x * 1024 + threadIdx.x;
    int v = (i < NN) ? g_count[i] : 0;
    if (i < NN) g_dinv[i] = rsqrtf((float)(v + 1));
    int s = v;
    for (int off = 16; off; off >>= 1) s += __shfl_xor_sync(0xffffffffu, s, off);
    __shared__ int sh[32];
    int l = threadIdx.x & 31, w = threadIdx.x >> 5;
    if (l == 0) sh[w] = s;
    __syncthreads();
    if (w == 0) {
        s = sh[l];
        for (int off = 16; off; off >>= 1) s += __shfl_xor_sync(0xffffffffu, s, off);
        if (l == 0) g_bsum[blockIdx.x] = s;
    }
}

__global__ void k_scan2() {
    int tid = threadIdx.x, l = tid & 31, w = tid >> 5;
    int v = (tid < 49) ? g_bsum[tid] : 0;
    int x = v;
    for (int off = 1; off < 32; off <<= 1) {
        int t = __shfl_up_sync(0xffffffffu, x, off);
        if (l >= off) x += t;
    }
    __shared__ int ws_[2];
    if (l == 31) ws_[w] = x;
    __syncthreads();
    if (w == 1) x += ws_[0];
    g_bsum[tid] = x - v;
    if (tid == 48) g_rowptr[NN] = x;
}

__global__ void k_scan3() {
    int i = blockIdx.x * 1024 + threadIdx.x;
    int v = (i < NN) ? g_count[i] : 0;
    int l = threadIdx.x & 31, w = threadIdx.x >> 5;
    int x = v;
    for (int off = 1; off < 32; off <<= 1) {
        int t = __shfl_up_sync(0xffffffffu, x, off);
        if (l >= off) x += t;
    }
    __shared__ int sh[32];
    if (l == 31) sh[w] = x;
    __syncthreads();
    if (w == 0) {
        int y = sh[l];
        for (int off = 1; off < 32; off <<= 1) {
            int t = __shfl_up_sync(0xffffffffu, y, off);
            if (l >= off) y += t;
        }
        sh[l] = y;
    }
    __syncthreads();
    int excl = x - v + ((w > 0) ? sh[w - 1] : 0);
    if (i < NN) g_rowptr[i] = g_bsum[blockIdx.x] + excl;
}

// ---------------- fused: scatter | packX + gemm1 ----------------
// blocks [0, scb): scatter edges (countdown slots via atomicSub on g_count)
// blocks [scb, scb+3125): pack 16 rows (ballot) then popc-GEMM from smem
__global__ void __launch_bounds__(512) k_scpg1(const void* __restrict__ ei, int E, int scb,
                                               const float* __restrict__ x) {
    __shared__ uint2 asv[16][NWX];
    __shared__ int   srt[16];
    __shared__ uint2 ws2[NWX * 64];
    __shared__ uint2 wv2[NWX * 64];
    int b = blockIdx.x, tid = threadIdx.x;
    if (b < scb) {                       // ---- scatter
        int e = b * 512 + tid;
        if (e < E) {
            int dst = edge_at(ei, 0, e, E);
            int src = edge_at(ei, 1, e, E);
            int old = atomicSub(&g_count[dst], 1);
            g_adj[g_rowptr[dst] + old - 1] =
                make_int2(src, __float_as_int(g_dinv[dst] * g_dinv[src]));
        }
        return;
    }
    // ---- pack + gemm1
    int wall = g_wall[0];
    {
        unsigned* u = (unsigned*)ws2;
        for (int i = tid; i < NWX * HID; i += 512) u[i] = g_w0s[i];
        if (!wall) {
            unsigned* v = (unsigned*)wv2;
            for (int i = tid; i < NWX * HID; i += 512) v[i] = g_w0v[i];
        }
    }
    int wid = tid >> 5, l = tid & 31;
    int r0 = (b - scb) * 16;
    int r = r0 + wid;
    const float inv_n = 1.0f / (float)NN;
    int tot = 0;
#pragma unroll
    for (int w = 0; w < NWX; w++) {
        int c = w * 32 + l;
        float t = __ldg(&x[r * INF + c]) - g_colsum[c] * inv_n;
        unsigned sb = __ballot_sync(0xffffffffu, t > 0.0f);
        unsigned vb = __ballot_sync(0xffffffffu, t != 0.0f);
        if (l == 0) { asv[wid][w] = make_uint2(sb, vb); tot += __popc(vb); }
    }
    if (l == 0) srt[wid] = tot;
    __syncthreads();
    int tx = tid & 63, ty = tid >> 6;    // ty 0..7; rows ty, ty+8; cols 2tx, 2tx+1
    int k00, k01, k10, k11;
    if (wall) {
        int p00 = 0, p01 = 0, p10 = 0, p11 = 0;
#pragma unroll
        for (int w = 0; w < NWX; w++) {
            uint2 aA = asv[ty][w], aB = asv[ty + 8][w];
            uint2 bb = ws2[w * 64 + tx];
            p00 += __popc(aA.y & ~(aA.x ^ bb.x));
            p01 += __popc(aA.y & ~(aA.x ^ bb.y));
            p10 += __popc(aB.y & ~(aB.x ^ bb.x));
            p11 += __popc(aB.y & ~(aB.x ^ bb.y));
        }
        int ra = srt[ty], rb = srt[ty + 8];
        k00 = 2 * p00 - ra; k01 = 2 * p01 - ra;
        k10 = 2 * p10 - rb; k11 = 2 * p11 - rb;
    } else {
        int p00 = 0, t00 = 0, p01 = 0, t01 = 0, p10 = 0, t10 = 0, p11 = 0, t11 = 0;
#pragma unroll
        for (int w = 0; w < NWX; w++) {
            uint2 aA = asv[ty][w], aB = asv[ty + 8][w];
            uint2 bb = ws2[w * 64 + tx];
            uint2 vv = wv2[w * 64 + tx];
            unsigned mA0 = aA.y & vv.x, mA1 = aA.y & vv.y;
            unsigned mB0 = aB.y & vv.x, mB1 = aB.y & vv.y;
            p00 += __popc(mA0 & ~(aA.x ^ bb.x)); t00 += __popc(mA0);
            p01 += __popc(mA1 & ~(aA.x ^ bb.y)); t01 += __popc(mA1);
            p10 += __popc(mB0 & ~(aB.x ^ bb.x)); t10 += __popc(mB0);
            p11 += __popc(mB1 & ~(aB.x ^ bb.y)); t11 += __popc(mB1);
        }
        k00 = 2 * p00 - t00; k01 = 2 * p01 - t01;
        k10 = 2 * p10 - t10; k11 = 2 * p11 - t11;
    }
    ((unsigned*)g_hk)[(r0 + ty) * 64 + tx] =
        (unsigned)(unsigned short)k00 | ((unsigned)(unsigned short)k01 << 16);
    ((unsigned*)g_hk)[(r0 + ty + 8) * 64 + tx] =
        (unsigned)(unsigned short)k10 | ((unsigned)(unsigned short)k11 << 16);
}

// ---------------- fused: aggregate + bias + dropout + pack + next GEMM (128 cols) ----------------
// layer = 0: in g_hk -> out g_hkB (weights w1); layer = 1: in g_hkB -> out g_h3k (weights w2)
__global__ void __launch_bounds__(256) k_agg_gemm(const float* __restrict__ bias, int layer,
                                                  float inv_n, unsigned fk0, unsigned fk1) {
    __shared__ uint2 ssv[8][NWH];
    __shared__ int   srt[8];
    __shared__ uint2 ws2[NWH * 64];
    __shared__ uint2 wv2[NWH * 64];
    int tid = threadIdx.x, wid = tid >> 5, l = tid & 31;
    int wall = g_wall[layer + 1];
    {
        const unsigned* wsrc = (layer == 0) ? g_w1s : g_w2s;
        const unsigned* wvsrc = (layer == 0) ? g_w1v : g_w2v;
        int nw = (layer == 0) ? NWH * HID : NWH * OUTF;
        if (tid < nw) {
            ((unsigned*)ws2)[tid] = wsrc[tid];
            if (!wall) ((unsigned*)wv2)[tid] = wvsrc[tid];
        }
        if (layer == 0 && tid + 256 < nw) {
            ((unsigned*)ws2)[tid + 256] = wsrc[tid + 256];
            if (!wall) ((unsigned*)wv2)[tid + 256] = wvsrc[tid + 256];
        }
    }
    int r = blockIdx.x * 8 + wid;
    float dr = g_dinv[r];
    float sw = dr * dr;
    const uint2* hrow = (const uint2*)((layer == 0) ? g_hk : g_hkB);
    uint2 hv = __ldg(&hrow[r * 32 + l]);
    int s0 = ((int)(hv.x << 16)) >> 16, s1 = (int)hv.x >> 16;
    int s2 = ((int)(hv.y << 16)) >> 16, s3 = (int)hv.y >> 16;
    float a0 = sw * (float)s0, a1 = sw * (float)s1;
    float a2 = sw * (float)s2, a3 = sw * (float)s3;
    int p = g_rowptr[r], pe = g_rowptr[r + 1];
    int2 e;
    if (p < pe) e = __ldg(&g_adj[p]);
    while (p < pe) {
        float w = __int_as_float(e.y);
        uint2 v = __ldg(&hrow[e.x * 32 + l]);
        if (++p < pe) e = __ldg(&g_adj[p]);
        int u0 = ((int)(v.x << 16)) >> 16, u1 = (int)v.x >> 16;
        int u2 = ((int)(v.y << 16)) >> 16, u3 = (int)v.y >> 16;
        a0 += w * (float)u0; a1 += w * (float)u1;
        a2 += w * (float)u2; a3 += w * (float)u3;
    }
    float alpha = g_araw[layer] * inv_n;
    float4 b4 = __ldg(&((const float4*)bias)[l]);
    float vv[4];
    vv[0] = alpha * a0 + b4.x;
    vv[1] = alpha * a1 + b4.y;
    vv[2] = alpha * a2 + b4.z;
    vv[3] = alpha * a3 + b4.w;
    unsigned base = (unsigned)(r * HID + 4 * l);
    unsigned sn = 0, vn = 0;
#pragma unroll
    for (int k = 0; k < 4; k++) {
        unsigned o0, o1;
        tf2x32_d(fk0, fk1, 0u, base + (unsigned)k, o0, o1);
        unsigned bits = o0 ^ o1;                    // jax partitionable path
        bool keep = ((int)bits >= 0);               // uniform < 0.5
        if (vv[k] > 0.0f) sn |= 1u << k;
        if (keep && vv[k] != 0.0f) vn |= 1u << k;
    }
    int sh = 4 * (l & 7);
    unsigned s4 = sn << sh, v4 = vn << sh;
    s4 |= __shfl_xor_sync(0xffffffffu, s4, 1);  v4 |= __shfl_xor_sync(0xffffffffu, v4, 1);
    s4 |= __shfl_xor_sync(0xffffffffu, s4, 2);  v4 |= __shfl_xor_sync(0xffffffffu, v4, 2);
    s4 |= __shfl_xor_sync(0xffffffffu, s4, 4);  v4 |= __shfl_xor_sync(0xffffffffu, v4, 4);
    int t = ((l & 7) == 0) ? __popc(v4) : 0;
    t += __shfl_xor_sync(0xffffffffu, t, 8);
    t += __shfl_xor_sync(0xffffffffu, t, 16);
    if ((l & 7) == 0) ssv[wid][l >> 3] = make_uint2(s4, v4);
    if (l == 0) srt[wid] = t;
    __syncthreads();
    // ---- in-block GEMM over the 8 freshly packed rows
    if (layer == 0) {                    // 8 rows x 128 cols -> g_hkB
        int tx = tid & 63, ty = tid >> 6;   // ty 0..3; rows ty, ty+4
        int k00, k01, k10, k11;
        if (wall) {
            int p00 = 0, p01 = 0, p10 = 0, p11 = 0;
#pragma unroll
            for (int w = 0; w < NWH; w++) {
                uint2 aA = ssv[ty][w], aB = ssv[ty + 4][w];
                uint2 bb = ws2[w * 64 + tx];
                p00 += __popc(aA.y & ~(aA.x ^ bb.x));
                p01 += __popc(aA.y & ~(aA.x ^ bb.y));
                p10 += __popc(aB.y & ~(aB.x ^ bb.x));
                p11 += __popc(aB.y & ~(aB.x ^ bb.y));
            }
            int ra = srt[ty], rb = srt[ty + 4];
            k00 = 2 * p00 - ra; k01 = 2 * p01 - ra;
            k10 = 2 * p10 - rb; k11 = 2 * p11 - rb;
        } else {
            int p00 = 0, t00 = 0, p01 = 0, t01 = 0, p10 = 0, t10 = 0, p11 = 0, t11 = 0;
#pragma unroll
            for (int w = 0; w < NWH; w++) {
                uint2 aA = ssv[ty][w], aB = ssv[ty + 4][w];
                uint2 bb = ws2[w * 64 + tx];
                uint2 vm = wv2[w * 64 + tx];
                unsigned mA0 = aA.y & vm.x, mA1 = aA.y & vm.y;
                unsigned mB0 = aB.y & vm.x, mB1 = aB.y & vm.y;
                p00 += __popc(mA0 & ~(aA.x ^ bb.x)); t00 += __popc(mA0);
                p01 += __popc(mA1 & ~(aA.x ^ bb.y)); t01 += __popc(mA1);
                p10 += __popc(mB0 & ~(aB.x ^ bb.x)); t10 += __popc(mB0);
                p11 += __popc(mB1 & ~(aB.x ^ bb.y)); t11 += __popc(mB1);
            }
            k00 = 2 * p00 - t00; k01 = 2 * p01 - t01;
            k10 = 2 * p10 - t10; k11 = 2 * p11 - t11;
        }
        int r0 = blockIdx.x * 8;
        ((unsigned*)g_hkB)[(r0 + ty) * 64 + tx] =
            (unsigned)(unsigned short)k00 | ((unsigned)(unsigned short)k01 << 16);
        ((unsigned*)g_hkB)[(r0 + ty + 4) * 64 + tx] =
            (unsigned)(unsigned short)k10 | ((unsigned)(unsigned short)k11 << 16);
    } else {                             // 8 rows x 40 cols -> g_h3k
        if (tid < 160) {
            int ty = tid / 20, tx = tid % 20;  // cols 2tx, 2tx+1
            int k0, k1;
            if (wall) {
                int p0 = 0, p1 = 0;
#pragma unroll
                for (int w = 0; w < NWH; w++) {
                    uint2 a = ssv[ty][w];
                    uint2 bb = ws2[w * 20 + tx];
                    p0 += __popc(a.y & ~(a.x ^ bb.x));
                    p1 += __popc(a.y & ~(a.x ^ bb.y));
                }
                int rt = srt[ty];
                k0 = 2 * p0 - rt; k1 = 2 * p1 - rt;
            } else {
                int p0 = 0, t0 = 0, p1 = 0, t1 = 0;
#pragma unroll
                for (int w = 0; w < NWH; w++) {
                    uint2 a = ssv[ty][w];
                    uint2 bb = ws2[w * 20 + tx];
                    uint2 vm = wv2[w * 20 + tx];
                    unsigned m0 = a.y & vm.x, m1 = a.y & vm.y;
                    p0 += __popc(m0 & ~(a.x ^ bb.x)); t0 += __popc(m0);
                    p1 += __popc(m1 & ~(a.x ^ bb.y)); t1 += __popc(m1);
                }
                k0 = 2 * p0 - t0; k1 = 2 * p1 - t1;
            }
            ((unsigned*)g_h3k)[(blockIdx.x * 8 + ty) * 20 + tx] =
                (unsigned)(unsigned short)k0 | ((unsigned)(unsigned short)k1 << 16);
        }
    }
}

// ---------------- final aggregate (40 int16 feats) + bias + log_softmax ----------------
__global__ void __launch_bounds__(256) k_agg_final(const float* __restrict__ bias,
                                                   float* __restrict__ out) {
    int wid = threadIdx.x >> 5, l = threadIdx.x & 31;
    int r = blockIdx.x * 8 + wid;
    float dr = g_dinv[r];
    float sw = dr * dr;
    const unsigned* hrow = (const unsigned*)g_h3k;
    bool act = (l < 20);
    float a0 = 0.0f, a1 = 0.0f;
    if (act) {
        unsigned u = __ldg(&hrow[r * 20 + l]);
        a0 = sw * (float)(((int)(u << 16)) >> 16);
        a1 = sw * (float)((int)u >> 16);
    }
    int p = g_rowptr[r], pe = g_rowptr[r + 1];
    int2 e;
    if (p < pe) e = __ldg(&g_adj[p]);
    while (p < pe) {
        float w = __int_as_float(e.y);
        unsigned u = act ? __ldg(&hrow[e.x * 20 + l]) : 0u;
        if (++p < pe) e = __ldg(&g_adj[p]);
        a0 += w * (float)(((int)(u << 16)) >> 16);
        a1 += w * (float)((int)u >> 16);
    }
    float alpha = g_araw[2] * (1.0f / (float)(HID * OUTF));
    float v0 = 0.0f, v1 = 0.0f;
    if (act) {
        float2 b2v = __ldg(&((const float2*)bias)[l]);
        v0 = alpha * a0 + b2v.x;
        v1 = alpha * a1 + b2v.y;
    }
    float m = act ? fmaxf(v0, v1) : -3.4e38f;
    for (int off = 16; off; off >>= 1) m = fmaxf(m, __shfl_xor_sync(0xffffffffu, m, off));
    float s = act ? (expf(v0 - m) + expf(v1 - m)) : 0.0f;
    for (int off = 16; off; off >>= 1) s += __shfl_xor_sync(0xffffffffu, s, off);
    float lse = m + logf(s);
    if (act) {
        float2 o; o.x = v0 - lse; o.y = v1 - lse;
        ((float2*)out)[r * 20 + l] = o;
    }
}

// ---------------- launch ----------------
extern "C" void kernel_launch(void* const* d_in, const int* in_sizes, int n_in,
                              void* d_out, int out_size) {
    const float* x  = (const float*)d_in[0];
    const void*  ei = d_in[1];
    const float* w0 = (const float*)d_in[2];
    const float* b0 = (const float*)d_in[3];
    const float* w1 = (const float*)d_in[4];
    const float* b1 = (const float*)d_in[5];
    const float* w2 = (const float*)d_in[6];
    const float* b2 = (const float*)d_in[7];
    float* out = (float*)d_out;
    int E = in_sizes[1] / 2;

    // dropout fold-in keys: fold_in(key(42), i) = threefry((0,42), (0,i))
    unsigned fk[2][2];
    for (int i = 0; i < 2; i++) tf2x32_h(0u, 42u, 0u, (unsigned)i, fk[i][0], fk[i][1]);

    k_init<<<(NN + 255) / 256, 256>>>((const unsigned*)ei);
    k_pre<<<261 + (E + 255) / 256, 256>>>(x, w0, w1, w2, ei, E);
    k_scan1<<<49, 1024>>>();
    k_scan2<<<1, 64>>>();
    k_scan3<<<49, 1024>>>();
    int scb = (E + 511) / 512;
    k_scpg1<<<scb + NN / 16, 512>>>(ei, E, scb, x);
    k_agg_gemm<<<NN / 8, 256>>>(b0, 0, 1.0f / (float)(INF * HID), fk[0][0], fk[0][1]);
    k_agg_gemm<<<NN / 8, 256>>>(b1, 1, 1.0f / (float)(HID * HID), fk[1][0], fk[1][1]);
    k_agg_final<<<NN / 8, 256>>>(b2, out);
}

// round 10
// speedup vs baseline: 1.7977x; 1.0870x over previous
#include <cuda_runtime.h>
#include <cuda_fp16.h>
#include <cstdint>

// ---------------- problem constants ----------------
#define NN    50000
#define INF   512
#define HID   128
#define OUTF  40
#define NWX   16      // INF/32 words per row
#define NWH   4       // HID/32 words per row
#define EE    600000
#define NPACKW (NWX*HID + NWH*HID + NWH*OUTF)   // 2720
#define CSB   250     // colsum partial blocks
#define PWB   11      // packw blocks

// ---------------- device scratch ----------------
__device__ float    g_csp[CSB * INF];   // colsum partials (plain stores)
__device__ float    g_cmean[INF];
__device__ float    g_arawp[PWB];
__device__ int      g_wallp[PWB];
__device__ float    g_alpha[3];         // mean(|w|) per layer
__device__ int      g_wall[3];          // 1 if ALL weight bits valid
__device__ __align__(16) unsigned g_w0s[NWX * HID];
__device__ __align__(16) unsigned g_w0v[NWX * HID];
__device__ __align__(16) unsigned g_w1s[NWH * HID];
__device__ __align__(16) unsigned g_w1v[NWH * HID];
__device__ __align__(16) unsigned g_w2s[NWH * OUTF];
__device__ __align__(16) unsigned g_w2v[NWH * OUTF];
__device__ int      g_count[NN];        // starts 0; count adds, scatter restores to 0
__device__ int      g_rowptr[NN + 1];
__device__ int      g_bsum[64];
__device__ float    g_dinv[NN];
__device__ __align__(16) int2    g_adj[EE];       // {src, w_bits}
__device__ __align__(16) __half2 g_hk[NN * 64];   // layer0 GEMM out (exact ints in fp16)
__device__ __align__(16) __half2 g_hkB[NN * 64];  // layer1 GEMM out
__device__ __align__(16) __half2 g_h3k[NN * 20];
__device__ int      g_is64;

// ---------------- threefry2x32 (jax-compatible) ----------------
__device__ __forceinline__ void tf2x32_d(unsigned k0, unsigned k1, unsigned c0, unsigned c1,
                                         unsigned& o0, unsigned& o1) {
    unsigned ks2 = k0 ^ k1 ^ 0x1BD11BDAu;
    unsigned x0 = c0 + k0, x1 = c1 + k1;
#define TFR_(r) { x0 += x1; x1 = __funnelshift_l(x1, x1, r); x1 ^= x0; }
    TFR_(13) TFR_(15) TFR_(26) TFR_(6)  x0 += k1;  x1 += ks2 + 1u;
    TFR_(17) TFR_(29) TFR_(16) TFR_(24) x0 += ks2; x1 += k0 + 2u;
    TFR_(13) TFR_(15) TFR_(26) TFR_(6)  x0 += k0;  x1 += k1 + 3u;
    TFR_(17) TFR_(29) TFR_(16) TFR_(24) x0 += k1;  x1 += ks2 + 4u;
    TFR_(13) TFR_(15) TFR_(26) TFR_(6)  x0 += ks2; x1 += k0 + 5u;
#undef TFR_
    o0 = x0; o1 = x1;
}

static void tf2x32_h(unsigned k0, unsigned k1, unsigned c0, unsigned c1,
                     unsigned& o0, unsigned& o1) {
    unsigned ks2 = k0 ^ k1 ^ 0x1BD11BDAu;
    unsigned x0 = c0 + k0, x1 = c1 + k1;
#define TFRH(r) { x0 += x1; x1 = (x1 << r) | (x1 >> (32 - r)); x1 ^= x0; }
    TFRH(13) TFRH(15) TFRH(26) TFRH(6)  x0 += k1;  x1 += ks2 + 1u;
    TFRH(17) TFRH(29) TFRH(16) TFRH(24) x0 += ks2; x1 += k0 + 2u;
    TFRH(13) TFRH(15) TFRH(26) TFRH(6)  x0 += k0;  x1 += k1 + 3u;
    TFRH(17) TFRH(29) TFRH(16) TFRH(24) x0 += k1;  x1 += ks2 + 4u;
    TFRH(13) TFRH(15) TFRH(26) TFRH(6)  x0 += ks2; x1 += k0 + 5u;
#undef TFRH
    o0 = x0; o1 = x1;
}

__device__ __forceinline__ int detect64(const unsigned* eb) {
    int ok = 1;
    for (int t = 0; t < 64; t++) if (eb[2 * t + 1] != 0u) { ok = 0; break; }
    return ok;
}

// ---------------- k_pre: colsum partials | packw | degree count ----------------
__global__ void __launch_bounds__(256) k_pre(const float* __restrict__ x,
                      const float* __restrict__ w0, const float* __restrict__ w1,
                      const float* __restrict__ w2,
                      const void* __restrict__ ei, int E) {
    int b = blockIdx.x, tid = threadIdx.x;
    if (b < CSB) {                       // ---- colsum partials: 200 rows/block, 2 cols/thread
        int c2 = tid;
        const float2* xp = (const float2*)x;
        float s0 = 0.0f, s1 = 0.0f;
        int r0 = b * 200;
        for (int r = r0; r < r0 + 200; r++) {
            float2 v = __ldg(&xp[r * (INF / 2) + c2]);
            s0 += v.x; s1 += v.y;
        }
        g_csp[b * INF + 2 * c2]     = s0;
        g_csp[b * INF + 2 * c2 + 1] = s1;
    } else if (b < CSB + PWB) {          // ---- packw (each block within one layer)
        __shared__ float sha[8];
        __shared__ int   shok;
        if (tid == 0) shok = 1;
        __syncthreads();
        int t = (b - CSB) * 256 + tid;
        bool valid = (t < NPACKW);
        const float* src = w0; int stride = HID, w = 0, j = 0;
        unsigned *ds = g_w0s, *dv = g_w0v;
        if (valid) {
            if (t < NWX * HID) {
                w = t >> 7; j = t & 127;
            } else if (t < NWX * HID + NWH * HID) {
                int u = t - NWX * HID;
                w = u >> 7; j = u & 127; src = w1; ds = g_w1s; dv = g_w1v;
            } else {
                int u = t - NWX * HID - NWH * HID;
                w = u / OUTF; j = u % OUTF; src = w2; stride = OUTF; ds = g_w2s; dv = g_w2v;
            }
        }
        unsigned sb = 0, vb = 0;
        float asum = 0.0f;
        if (valid) {
#pragma unroll 8
            for (int i = 0; i < 32; i++) {
                float v = __ldg(&src[(w * 32 + i) * stride + j]);
                sb |= (v > 0.0f ? 1u : 0u) << i;
                vb |= (v != 0.0f ? 1u : 0u) << i;
                asum += fabsf(v);
            }
            ds[w * stride + j] = sb;
            dv[w * stride + j] = vb;
            if (vb != 0xffffffffu) atomicAnd(&shok, 0);
        }
        for (int off = 16; off; off >>= 1) asum += __shfl_xor_sync(0xffffffffu, asum, off);
        if ((tid & 31) == 0) sha[tid >> 5] = asum;
        __syncthreads();
        if (tid == 0) {
            float s = 0.0f;
            for (int i = 0; i < 8; i++) s += sha[i];
            g_arawp[b - CSB] = s;
            g_wallp[b - CSB] = shok;
        }
    } else {                             // ---- degree count (local is64 detect)
        __shared__ int sis;
        if (tid == 0) sis = detect64((const unsigned*)ei);
        __syncthreads();
        int e = (b - CSB - PWB) * 256 + tid;
        if (e < E) {
            int dst = sis ? (int)((const long long*)ei)[e] : ((const int*)ei)[e];
            atomicAdd(&g_count[dst], 1);
        }
    }
}

// ---------------- k_scanA: per-block sums + dinv | colmean | alpha/wall | is64 ----------------
__global__ void __launch_bounds__(1024) k_scanA(const void* __restrict__ ei) {
    int b = blockIdx.x;
    if (b < 49) {
        int i = b * 1024 + threadIdx.x;
        int v = (i < NN) ? g_count[i] : 0;
        if (i < NN) g_dinv[i] = rsqrtf((float)(v + 1));
        int s = v;
        for (int off = 16; off; off >>= 1) s += __shfl_xor_sync(0xffffffffu, s, off);
        __shared__ int sh[32];
        int l = threadIdx.x & 31, w = threadIdx.x >> 5;
        if (l == 0) sh[w] = s;
        __syncthreads();
        if (w == 0) {
            s = sh[l];
            for (int off = 16; off; off >>= 1) s += __shfl_xor_sync(0xffffffffu, s, off);
            if (l == 0) g_bsum[b] = s;
        }
    } else if (b == 49) {                // column means
        int c = threadIdx.x;
        if (c < INF) {
            float s = 0.0f;
            for (int i = 0; i < CSB; i++) s += g_csp[i * INF + c];
            g_cmean[c] = s * (1.0f / (float)NN);
        }
    } else if (b == 50) {                // alpha + wall
        if (threadIdx.x == 0) {
            float s0 = 0, s1 = 0, s2 = 0; int k0 = 1, k1 = 1, k2 = 1;
            for (int i = 0; i < 8; i++)  { s0 += g_arawp[i]; k0 &= g_wallp[i]; }
            for (int i = 8; i < 10; i++) { s1 += g_arawp[i]; k1 &= g_wallp[i]; }
            s2 = g_arawp[10]; k2 = g_wallp[10];
            g_alpha[0] = s0 * (1.0f / (float)(INF * HID));
            g_alpha[1] = s1 * (1.0f / (float)(HID * HID));
            g_alpha[2] = s2 * (1.0f / (float)(HID * OUTF));
            g_wall[0] = k0; g_wall[1] = k1; g_wall[2] = k2;
        }
    } else {                             // is64 (for scatter)
        if (threadIdx.x == 0) g_is64 = detect64((const unsigned*)ei);
    }
}

// ---------------- k_scanB: local 49-scan + rowptr ----------------
__global__ void __launch_bounds__(1024) k_scanB() {
    __shared__ int sp[64];
    __shared__ int sh[32];
    int tid = threadIdx.x, l = tid & 31, w = tid >> 5;
    if (w == 0) {                        // warp 0: scan the 49 block sums
        int a0 = g_bsum[l];
        int a1 = (l < 17) ? g_bsum[32 + l] : 0;
        int i0 = a0, i1 = a1;
        for (int off = 1; off < 32; off <<= 1) {
            int t0 = __shfl_up_sync(0xffffffffu, i0, off);
            int t1 = __shfl_up_sync(0xffffffffu, i1, off);
            if (l >= off) { i0 += t0; i1 += t1; }
        }
        int tot0 = __shfl_sync(0xffffffffu, i0, 31);
        sp[l]      = i0 - a0;
        sp[32 + l] = i1 - a1 + tot0;
        int grand = __shfl_sync(0xffffffffu, i1, 16) + tot0;
        if (l == 0 && blockIdx.x == 48) g_rowptr[NN] = grand;
    }
    __syncthreads();
    int base = sp[blockIdx.x];
    int i = blockIdx.x * 1024 + tid;
    int v = (i < NN) ? g_count[i] : 0;
    int x = v;
    for (int off = 1; off < 32; off <<= 1) {
        int t = __shfl_up_sync(0xffffffffu, x, off);
        if (l >= off) x += t;
    }
    if (l == 31) sh[w] = x;
    __syncthreads();
    if (w == 0) {
        int y = sh[l];
        for (int off = 1; off < 32; off <<= 1) {
            int t = __shfl_up_sync(0xffffffffu, y, off);
            if (l >= off) y += t;
        }
        sh[l] = y;
    }
    __syncthreads();
    int excl = x - v + ((w > 0) ? sh[w - 1] : 0);
    if (i < NN) g_rowptr[i] = base + excl;
}

// ---------------- fused: scatter | packX + gemm1 ----------------
__global__ void __launch_bounds__(512) k_scpg1(const void* __restrict__ ei, int E, int scb,
                                               const float* __restrict__ x) {
    __shared__ uint2 asv[16][NWX];
    __shared__ int   srt[16];
    __shared__ uint2 ws2[NWX * 64];
    __shared__ uint2 wv2[NWX * 64];
    int b = blockIdx.x, tid = threadIdx.x;
    if (b < scb) {                       // ---- scatter (countdown restores g_count to 0)
        int e = b * 512 + tid;
        if (e < E) {
            int is64 = g_is64;
            int dst, src;
            if (is64) {
                dst = (int)((const long long*)ei)[e];
                src = (int)((const long long*)ei)[(size_t)E + e];
            } else {
                dst = ((const int*)ei)[e];
                src = ((const int*)ei)[E + e];
            }
            int old = atomicSub(&g_count[dst], 1);
            g_adj[g_rowptr[dst] + old - 1] =
                make_int2(src, __float_as_int(g_dinv[dst] * g_dinv[src]));
        }
        return;
    }
    // ---- pack + gemm1
    int wall = g_wall[0];
    {
        unsigned* u = (unsigned*)ws2;
        for (int i = tid; i < NWX * HID; i += 512) u[i] = g_w0s[i];
        if (!wall) {
            unsigned* v = (unsigned*)wv2;
            for (int i = tid; i < NWX * HID; i += 512) v[i] = g_w0v[i];
        }
    }
    int wid = tid >> 5, l = tid & 31;
    int r0 = (b - scb) * 16;
    int r = r0 + wid;
    int tot = 0;
#pragma unroll
    for (int w = 0; w < NWX; w++) {
        int c = w * 32 + l;
        float t = __ldg(&x[r * INF + c]) - g_cmean[c];
        unsigned sb = __ballot_sync(0xffffffffu, t > 0.0f);
        unsigned vb = __ballot_sync(0xffffffffu, t != 0.0f);
        if (l == 0) { asv[wid][w] = make_uint2(sb, vb); tot += __popc(vb); }
    }
    if (l == 0) srt[wid] = tot;
    __syncthreads();
    int tx = tid & 63, ty = tid >> 6;    // rows ty, ty+8; cols 2tx, 2tx+1
    int k00, k01, k10, k11;
    if (wall) {
        int p00 = 0, p01 = 0, p10 = 0, p11 = 0;
#pragma unroll
        for (int w = 0; w < NWX; w++) {
            uint2 aA = asv[ty][w], aB = asv[ty + 8][w];
            uint2 bb = ws2[w * 64 + tx];
            p00 += __popc(aA.y & ~(aA.x ^ bb.x));
            p01 += __popc(aA.y & ~(aA.x ^ bb.y));
            p10 += __popc(aB.y & ~(aB.x ^ bb.x));
            p11 += __popc(aB.y & ~(aB.x ^ bb.y));
        }
        int ra = srt[ty], rb = srt[ty + 8];
        k00 = 2 * p00 - ra; k01 = 2 * p01 - ra;
        k10 = 2 * p10 - rb; k11 = 2 * p11 - rb;
    } else {
        int p00 = 0, t00 = 0, p01 = 0, t01 = 0, p10 = 0, t10 = 0, p11 = 0, t11 = 0;
#pragma unroll
        for (int w = 0; w < NWX; w++) {
            uint2 aA = asv[ty][w], aB = asv[ty + 8][w];
            uint2 bb = ws2[w * 64 + tx];
            uint2 vv = wv2[w * 64 + tx];
            unsigned mA0 = aA.y & vv.x, mA1 = aA.y & vv.y;
            unsigned mB0 = aB.y & vv.x, mB1 = aB.y & vv.y;
            p00 += __popc(mA0 & ~(aA.x ^ bb.x)); t00 += __popc(mA0);
            p01 += __popc(mA1 & ~(aA.x ^ bb.y)); t01 += __popc(mA1);
            p10 += __popc(mB0 & ~(aB.x ^ bb.x)); t10 += __popc(mB0);
            p11 += __popc(mB1 & ~(aB.x ^ bb.y)); t11 += __popc(mB1);
        }
        k00 = 2 * p00 - t00; k01 = 2 * p01 - t01;
        k10 = 2 * p10 - t10; k11 = 2 * p11 - t11;
    }
    g_hk[(r0 + ty) * 64 + tx]     = __floats2half2_rn((float)k00, (float)k01);
    g_hk[(r0 + ty + 8) * 64 + tx] = __floats2half2_rn((float)k10, (float)k11);
}

// ---------------- fused: aggregate + bias + dropout + pack + next GEMM ----------------
__global__ void __launch_bounds__(256) k_agg_gemm(const float* __restrict__ bias, int layer,
                                                  unsigned fk0, unsigned fk1) {
    __shared__ uint2 ssv[8][NWH];
    __shared__ int   srt[8];
    __shared__ uint2 ws2[NWH * 64];
    __shared__ uint2 wv2[NWH * 64];
    int tid = threadIdx.x, wid = tid >> 5, l = tid & 31;
    int wall = g_wall[layer + 1];
    {
        const unsigned* wsrc = (layer == 0) ? g_w1s : g_w2s;
        const unsigned* wvsrc = (layer == 0) ? g_w1v : g_w2v;
        int nw = (layer == 0) ? NWH * HID : NWH * OUTF;
        if (tid < nw) {
            ((unsigned*)ws2)[tid] = wsrc[tid];
            if (!wall) ((unsigned*)wv2)[tid] = wvsrc[tid];
        }
        if (layer == 0 && tid + 256 < nw) {
            ((unsigned*)ws2)[tid + 256] = wsrc[tid + 256];
            if (!wall) ((unsigned*)wv2)[tid + 256] = wvsrc[tid + 256];
        }
    }
    int r = blockIdx.x * 8 + wid;
    float dr = g_dinv[r];
    float sw = dr * dr;
    const uint2* hrow = (const uint2*)((layer == 0) ? g_hk : g_hkB);
    uint2 hv = __ldg(&hrow[r * 32 + l]);
    float2 f01 = __half22float2(*(__half2*)&hv.x);
    float2 f23 = __half22float2(*(__half2*)&hv.y);
    float a0 = sw * f01.x, a1 = sw * f01.y;
    float a2 = sw * f23.x, a3 = sw * f23.y;
    int p = g_rowptr[r], pe = g_rowptr[r + 1];
    int2 e;
    if (p < pe) e = __ldg(&g_adj[p]);
    while (p < pe) {
        float w = __int_as_float(e.y);
        uint2 v = __ldg(&hrow[e.x * 32 + l]);
        if (++p < pe) e = __ldg(&g_adj[p]);
        float2 u01 = __half22float2(*(__half2*)&v.x);
        float2 u23 = __half22float2(*(__half2*)&v.y);
        a0 += w * u01.x; a1 += w * u01.y;
        a2 += w * u23.x; a3 += w * u23.y;
    }
    float alpha = g_alpha[layer];
    float4 b4 = __ldg(&((const float4*)bias)[l]);
    float vv[4];
    vv[0] = alpha * a0 + b4.x;
    vv[1] = alpha * a1 + b4.y;
    vv[2] = alpha * a2 + b4.z;
    vv[3] = alpha * a3 + b4.w;
    unsigned base = (unsigned)(r * HID + 4 * l);
    unsigned sn = 0, vn = 0;
#pragma unroll
    for (int k = 0; k < 4; k++) {
        unsigned o0, o1;
        tf2x32_d(fk0, fk1, 0u, base + (unsigned)k, o0, o1);
        unsigned bits = o0 ^ o1;                    // jax partitionable path
        bool keep = ((int)bits >= 0);               // uniform < 0.5
        if (vv[k] > 0.0f) sn |= 1u << k;
        if (keep && vv[k] != 0.0f) vn |= 1u << k;
    }
    int sh = 4 * (l & 7);
    unsigned s4 = sn << sh, v4 = vn << sh;
    s4 |= __shfl_xor_sync(0xffffffffu, s4, 1);  v4 |= __shfl_xor_sync(0xffffffffu, v4, 1);
    s4 |= __shfl_xor_sync(0xffffffffu, s4, 2);  v4 |= __shfl_xor_sync(0xffffffffu, v4, 2);
    s4 |= __shfl_xor_sync(0xffffffffu, s4, 4);  v4 |= __shfl_xor_sync(0xffffffffu, v4, 4);
    int t = ((l & 7) == 0) ? __popc(v4) : 0;
    t += __shfl_xor_sync(0xffffffffu, t, 8);
    t += __shfl_xor_sync(0xffffffffu, t, 16);
    if ((l & 7) == 0) ssv[wid][l >> 3] = make_uint2(s4, v4);
    if (l == 0) srt[wid] = t;
    __syncthreads();
    // ---- in-block GEMM over the 8 freshly packed rows
    if (layer == 0) {                    // 8 rows x 128 cols -> g_hkB
        int tx = tid & 63, ty = tid >> 6;   // rows ty, ty+4
        int k00, k01, k10, k11;
        if (wall) {
            int p00 = 0, p01 = 0, p10 = 0, p11 = 0;
#pragma unroll
            for (int w = 0; w < NWH; w++) {
                uint2 aA = ssv[ty][w], aB = ssv[ty + 4][w];
                uint2 bb = ws2[w * 64 + tx];
                p00 += __popc(aA.y & ~(aA.x ^ bb.x));
                p01 += __popc(aA.y & ~(aA.x ^ bb.y));
                p10 += __popc(aB.y & ~(aB.x ^ bb.x));
                p11 += __popc(aB.y & ~(aB.x ^ bb.y));
            }
            int ra = srt[ty], rb = srt[ty + 4];
            k00 = 2 * p00 - ra; k01 = 2 * p01 - ra;
            k10 = 2 * p10 - rb; k11 = 2 * p11 - rb;
        } else {
            int p00 = 0, t00 = 0, p01 = 0, t01 = 0, p10 = 0, t10 = 0, p11 = 0, t11 = 0;
#pragma unroll
            for (int w = 0; w < NWH; w++) {
                uint2 aA = ssv[ty][w], aB = ssv[ty + 4][w];
                uint2 bb = ws2[w * 64 + tx];
                uint2 vm = wv2[w * 64 + tx];
                unsigned mA0 = aA.y & vm.x, mA1 = aA.y & vm.y;
                unsigned mB0 = aB.y & vm.x, mB1 = aB.y & vm.y;
                p00 += __popc(mA0 & ~(aA.x ^ bb.x)); t00 += __popc(mA0);
                p01 += __popc(mA1 & ~(aA.x ^ bb.y)); t01 += __popc(mA1);
                p10 += __popc(mB0 & ~(aB.x ^ bb.x)); t10 += __popc(mB0);
                p11 += __popc(mB1 & ~(aB.x ^ bb.y)); t11 += __popc(mB1);
            }
            k00 = 2 * p00 - t00; k01 = 2 * p01 - t01;
            k10 = 2 * p10 - t10; k11 = 2 * p11 - t11;
        }
        int r0 = blockIdx.x * 8;
        g_hkB[(r0 + ty) * 64 + tx]     = __floats2half2_rn((float)k00, (float)k01);
        g_hkB[(r0 + ty + 4) * 64 + tx] = __floats2half2_rn((float)k10, (float)k11);
    } else {                             // 8 rows x 40 cols -> g_h3k
        if (tid < 160) {
            int ty = tid / 20, tx = tid % 20;  // cols 2tx, 2tx+1
            int k0, k1;
            if (wall) {
                int p0 = 0, p1 = 0;
#pragma unroll
                for (int w = 0; w < NWH; w++) {
                    uint2 a = ssv[ty][w];
                    uint2 bb = ws2[w * 20 + tx];
                    p0 += __popc(a.y & ~(a.x ^ bb.x));
                    p1 += __popc(a.y & ~(a.x ^ bb.y));
                }
                int rt = srt[ty];
                k0 = 2 * p0 - rt; k1 = 2 * p1 - rt;
            } else {
                int p0 = 0, t0 = 0, p1 = 0, t1 = 0;
#pragma unroll
                for (int w = 0; w < NWH; w++) {
                    uint2 a = ssv[ty][w];
                    uint2 bb = ws2[w * 20 + tx];
                    uint2 vm = wv2[w * 20 + tx];
                    unsigned m0 = a.y & vm.x, m1 = a.y & vm.y;
                    p0 += __popc(m0 & ~(a.x ^ bb.x)); t0 += __popc(m0);
                    p1 += __popc(m1 & ~(a.x ^ bb.y)); t1 += __popc(m1);
                }
                k0 = 2 * p0 - t0; k1 = 2 * p1 - t1;
            }
            g_h3k[(blockIdx.x * 8 + ty) * 20 + tx] = __floats2half2_rn((float)k0, (float)k1);
        }
    }
}

// ---------------- final aggregate + bias + log_softmax ----------------
__global__ void __launch_bounds__(256) k_agg_final(const float* __restrict__ bias,
                                                   float* __restrict__ out) {
    int wid = threadIdx.x >> 5, l = threadIdx.x & 31;
    int r = blockIdx.x * 8 + wid;
    float dr = g_dinv[r];
    float sw = dr * dr;
    bool act = (l < 20);
    float a0 = 0.0f, a1 = 0.0f;
    if (act) {
        float2 f = __half22float2(__ldg(&g_h3k[r * 20 + l]));
        a0 = sw * f.x; a1 = sw * f.y;
    }
    int p = g_rowptr[r], pe = g_rowptr[r + 1];
    int2 e;
    if (p < pe) e = __ldg(&g_adj[p]);
    while (p < pe) {
        float w = __int_as_float(e.y);
        __half2 u = act ? __ldg(&g_h3k[e.x * 20 + l]) : __half2();
        if (++p < pe) e = __ldg(&g_adj[p]);
        float2 f = __half22float2(u);
        a0 += w * f.x; a1 += w * f.y;
    }
    float alpha = g_alpha[2];
    float v0 = 0.0f, v1 = 0.0f;
    if (act) {
        float2 b2v = __ldg(&((const float2*)bias)[l]);
        v0 = alpha * a0 + b2v.x;
        v1 = alpha * a1 + b2v.y;
    }
    float m = act ? fmaxf(v0, v1) : -3.4e38f;
    for (int off = 16; off; off >>= 1) m = fmaxf(m, __shfl_xor_sync(0xffffffffu, m, off));
    float s = act ? (expf(v0 - m) + expf(v1 - m)) : 0.0f;
    for (int off = 16; off; off >>= 1) s += __shfl_xor_sync(0xffffffffu, s, off);
    float lse = m + logf(s);
    if (act) {
        float2 o; o.x = v0 - lse; o.y = v1 - lse;
        ((float2*)out)[r * 20 + l] = o;
    }
}

// ---------------- launch ----------------
extern "C" void kernel_launch(void* const* d_in, const int* in_sizes, int n_in,
                              void* d_out, int out_size) {
    const float* x  = (const float*)d_in[0];
    const void*  ei = d_in[1];
    const float* w0 = (const float*)d_in[2];
    const float* b0 = (const float*)d_in[3];
    const float* w1 = (const float*)d_in[4];
    const float* b1 = (const float*)d_in[5];
    const float* w2 = (const float*)d_in[6];
    const float* b2 = (const float*)d_in[7];
    float* out = (float*)d_out;
    int E = in_sizes[1] / 2;

    // dropout fold-in keys: fold_in(key(42), i) = threefry((0,42), (0,i))
    unsigned fk[2][2];
    for (int i = 0; i < 2; i++) tf2x32_h(0u, 42u, 0u, (unsigned)i, fk[i][0], fk[i][1]);

    k_pre<<<CSB + PWB + (E + 255) / 256, 256>>>(x, w0, w1, w2, ei, E);
    k_scanA<<<52, 1024>>>(ei);
    k_scanB<<<49, 1024>>>();
    int scb = (E + 511) / 512;
    k_scpg1<<<scb + NN / 16, 512>>>(ei, E, scb, x);
    k_agg_gemm<<<NN / 8, 256>>>(b0, 0, fk[0][0], fk[0][1]);
    k_agg_gemm<<<NN / 8, 256>>>(b1, 1, fk[1][0], fk[1][1]);
    k_agg_final<<<NN / 8, 256>>>(b2, out);
}

// round 12
// speedup vs baseline: 1.8004x; 1.0015x over previous
#include <cuda_runtime.h>
#include <cuda_fp16.h>
#include <cstdint>

// ---------------- problem constants ----------------
#define NN    50000
#define INF   512
#define HID   128
#define OUTF  40
#define NWX   16      // INF/32 words per row
#define NWH   4       // HID/32 words per row
#define EE    600000
#define NPACKW (NWX*HID + NWH*HID + NWH*OUTF)   // 2720
#define CSB   250     // colsum row-chunks (200 rows each)
#define PWB   11      // packw blocks
#define CSBLK 500     // colsum blocks (chunk x col-half)
#define PACKB (NN/16) // 3125 pack+gemm1 blocks

// ---------------- device scratch ----------------
__device__ float    g_csp[CSB * INF];   // colsum partials (plain stores)
__device__ float    g_cmean[INF];
__device__ float    g_arawp[PWB];
__device__ int      g_wallp[PWB];
__device__ float    g_alpha[3];         // mean(|w|) per layer
__device__ int      g_wall[3];          // 1 if ALL weight bits valid
__device__ __align__(16) unsigned g_w0s[NWX * HID];
__device__ __align__(16) unsigned g_w0v[NWX * HID];
__device__ __align__(16) unsigned g_w1s[NWH * HID];
__device__ __align__(16) unsigned g_w1v[NWH * HID];
__device__ __align__(16) unsigned g_w2s[NWH * OUTF];
__device__ __align__(16) unsigned g_w2v[NWH * OUTF];
__device__ int      g_count[NN];        // starts 0; count adds, scatter restores to 0
__device__ int      g_rowptr[NN + 1];
__device__ int      g_bsum[64];
__device__ float    g_dinv[NN];
__device__ __align__(128) int2    g_adj[EE];       // {src, w_bits}
__device__ __align__(128) __half2 g_hk[NN * 64];   // layer0 GEMM out (exact ints in fp16)
__device__ __align__(128) __half2 g_hkB[NN * 64];  // layer1 GEMM out
__device__ __align__(128) __half2 g_h3k[NN * 20];
__device__ int      g_is64;

// ---------------- threefry2x32 (jax-compatible) ----------------
__device__ __forceinline__ void tf2x32_d(unsigned k0, unsigned k1, unsigned c0, unsigned c1,
                                         unsigned& o0, unsigned& o1) {
    unsigned ks2 = k0 ^ k1 ^ 0x1BD11BDAu;
    unsigned x0 = c0 + k0, x1 = c1 + k1;
#define TFR_(r) { x0 += x1; x1 = __funnelshift_l(x1, x1, r); x1 ^= x0; }
    TFR_(13) TFR_(15) TFR_(26) TFR_(6)  x0 += k1;  x1 += ks2 + 1u;
    TFR_(17) TFR_(29) TFR_(16) TFR_(24) x0 += ks2; x1 += k0 + 2u;
    TFR_(13) TFR_(15) TFR_(26) TFR_(6)  x0 += k0;  x1 += k1 + 3u;
    TFR_(17) TFR_(29) TFR_(16) TFR_(24) x0 += k1;  x1 += ks2 + 4u;
    TFR_(13) TFR_(15) TFR_(26) TFR_(6)  x0 += ks2; x1 += k0 + 5u;
#undef TFR_
    o0 = x0; o1 = x1;
}

static void tf2x32_h(unsigned k0, unsigned k1, unsigned c0, unsigned c1,
                     unsigned& o0, unsigned& o1) {
    unsigned ks2 = k0 ^ k1 ^ 0x1BD11BDAu;
    unsigned x0 = c0 + k0, x1 = c1 + k1;
#define TFRH(r) { x0 += x1; x1 = (x1 << r) | (x1 >> (32 - r)); x1 ^= x0; }
    TFRH(13) TFRH(15) TFRH(26) TFRH(6)  x0 += k1;  x1 += ks2 + 1u;
    TFRH(17) TFRH(29) TFRH(16) TFRH(24) x0 += ks2; x1 += k0 + 2u;
    TFRH(13) TFRH(15) TFRH(26) TFRH(6)  x0 += k0;  x1 += k1 + 3u;
    TFRH(17) TFRH(29) TFRH(16) TFRH(24) x0 += k1;  x1 += ks2 + 4u;
    TFRH(13) TFRH(15) TFRH(26) TFRH(6)  x0 += ks2; x1 += k0 + 5u;
#undef TFRH
    o0 = x0; o1 = x1;
}

__device__ __forceinline__ int detect64(const unsigned* eb) {
    int ok = 1;
    for (int t = 0; t < 64; t++) if (eb[2 * t + 1] != 0u) { ok = 0; break; }
    return ok;
}

// ---------------- k_pre: colsum partials | packw | degree count ----------------
__global__ void __launch_bounds__(256) k_pre(const float* __restrict__ x,
                      const float* __restrict__ w0, const float* __restrict__ w1,
                      const float* __restrict__ w2,
                      const void* __restrict__ ei, int E) {
    int b = blockIdx.x, tid = threadIdx.x;
    if (b < CSBLK) {                     // ---- colsum partials: 200 rows x 256 cols per block
        int chunk = b >> 1;
        int col = (b & 1) * 256 + tid;
        int r0 = chunk * 200;
        float s = 0.0f;
#pragma unroll 8
        for (int r = 0; r < 200; r++)
            s += __ldg(&x[(size_t)(r0 + r) * INF + col]);
        g_csp[chunk * INF + col] = s;
    } else if (b < CSBLK + PWB) {        // ---- packw
        __shared__ float sha[8];
        __shared__ int   shok;
        if (tid == 0) shok = 1;
        __syncthreads();
        int t = (b - CSBLK) * 256 + tid;
        bool valid = (t < NPACKW);
        const float* src = w0; int stride = HID, w = 0, j = 0;
        unsigned *ds = g_w0s, *dv = g_w0v;
        if (valid) {
            if (t < NWX * HID) {
                w = t >> 7; j = t & 127;
            } else if (t < NWX * HID + NWH * HID) {
                int u = t - NWX * HID;
                w = u >> 7; j = u & 127; src = w1; ds = g_w1s; dv = g_w1v;
            } else {
                int u = t - NWX * HID - NWH * HID;
                w = u / OUTF; j = u % OUTF; src = w2; stride = OUTF; ds = g_w2s; dv = g_w2v;
            }
        }
        unsigned sb = 0, vb = 0;
        float asum = 0.0f;
        if (valid) {
#pragma unroll 8
            for (int i = 0; i < 32; i++) {
                float v = __ldg(&src[(w * 32 + i) * stride + j]);
                sb |= (v > 0.0f ? 1u : 0u) << i;
                vb |= (v != 0.0f ? 1u : 0u) << i;
                asum += fabsf(v);
            }
            ds[w * stride + j] = sb;
            dv[w * stride + j] = vb;
            if (vb != 0xffffffffu) atomicAnd(&shok, 0);
        }
        for (int off = 16; off; off >>= 1) asum += __shfl_xor_sync(0xffffffffu, asum, off);
        if ((tid & 31) == 0) sha[tid >> 5] = asum;
        __syncthreads();
        if (tid == 0) {
            float s = 0.0f;
            for (int i = 0; i < 8; i++) s += sha[i];
            g_arawp[b - CSBLK] = s;
            g_wallp[b - CSBLK] = shok;
        }
    } else {                             // ---- degree count (local is64 detect)
        __shared__ int sis;
        if (tid == 0) sis = detect64((const unsigned*)ei);
        __syncthreads();
        int e = (b - CSBLK - PWB) * 256 + tid;
        if (e < E) {
            int dst = sis ? (int)((const long long*)ei)[e] : ((const int*)ei)[e];
            atomicAdd(&g_count[dst], 1);
        }
    }
}

// ---------------- k_scanA: block sums + dinv | colmean x2 | alpha/wall | is64 ----------------
__global__ void __launch_bounds__(1024) k_scanA(const void* __restrict__ ei) {
    int b = blockIdx.x;
    if (b < 49) {
        int i = b * 1024 + threadIdx.x;
        int v = (i < NN) ? g_count[i] : 0;
        if (i < NN) g_dinv[i] = rsqrtf((float)(v + 1));
        int s = v;
        for (int off = 16; off; off >>= 1) s += __shfl_xor_sync(0xffffffffu, s, off);
        __shared__ int sh[32];
        int l = threadIdx.x & 31, w = threadIdx.x >> 5;
        if (l == 0) sh[w] = s;
        __syncthreads();
        if (w == 0) {
            s = sh[l];
            for (int off = 16; off; off >>= 1) s += __shfl_xor_sync(0xffffffffu, s, off);
            if (l == 0) g_bsum[b] = s;
        }
    } else if (b < 51) {                 // column means: 2 blocks x 256 cols, 4-way split
        __shared__ float red[4][256];
        int cl = threadIdx.x & 255, g = threadIdx.x >> 8;
        int c = (b - 49) * 256 + cl;
        float s = 0.0f;
        for (int i = g; i < CSB; i += 4) s += g_csp[i * INF + c];
        red[g][cl] = s;
        __syncthreads();
        if (g == 0)
            g_cmean[c] = (red[0][cl] + red[1][cl] + red[2][cl] + red[3][cl])
                         * (1.0f / (float)NN);
    } else if (b == 51) {                // alpha + wall
        if (threadIdx.x == 0) {
            float s0 = 0, s1 = 0, s2 = 0; int k0 = 1, k1 = 1, k2 = 1;
            for (int i = 0; i < 8; i++)  { s0 += g_arawp[i]; k0 &= g_wallp[i]; }
            for (int i = 8; i < 10; i++) { s1 += g_arawp[i]; k1 &= g_wallp[i]; }
            s2 = g_arawp[10]; k2 = g_wallp[10];
            g_alpha[0] = s0 * (1.0f / (float)(INF * HID));
            g_alpha[1] = s1 * (1.0f / (float)(HID * HID));
            g_alpha[2] = s2 * (1.0f / (float)(HID * OUTF));
            g_wall[0] = k0; g_wall[1] = k1; g_wall[2] = k2;
        }
    } else {                             // is64 (for scatter)
        if (threadIdx.x == 0) g_is64 = detect64((const unsigned*)ei);
    }
}

// ---------------- k_scanB: local 49-scan + rowptr ----------------
__global__ void __launch_bounds__(1024) k_scanB() {
    __shared__ int sp[64];
    __shared__ int sh[32];
    int tid = threadIdx.x, l = tid & 31, w = tid >> 5;
    if (w == 0) {                        // warp 0: scan the 49 block sums
        int a0 = g_bsum[l];
        int a1 = (l < 17) ? g_bsum[32 + l] : 0;
        int i0 = a0, i1 = a1;
        for (int off = 1; off < 32; off <<= 1) {
            int t0 = __shfl_up_sync(0xffffffffu, i0, off);
            int t1 = __shfl_up_sync(0xffffffffu, i1, off);
            if (l >= off) { i0 += t0; i1 += t1; }
        }
        int tot0 = __shfl_sync(0xffffffffu, i0, 31);
        sp[l]      = i0 - a0;
        sp[32 + l] = i1 - a1 + tot0;
        int grand = __shfl_sync(0xffffffffu, i1, 16) + tot0;
        if (l == 0 && blockIdx.x == 48) g_rowptr[NN] = grand;
    }
    __syncthreads();
    int base = sp[blockIdx.x];
    int i = blockIdx.x * 1024 + tid;
    int v = (i < NN) ? g_count[i] : 0;
    int x = v;
    for (int off = 1; off < 32; off <<= 1) {
        int t = __shfl_up_sync(0xffffffffu, x, off);
        if (l >= off) x += t;
    }
    if (l == 31) sh[w] = x;
    __syncthreads();
    if (w == 0) {
        int y = sh[l];
        for (int off = 1; off < 32; off <<= 1) {
            int t = __shfl_up_sync(0xffffffffu, y, off);
            if (l >= off) y += t;
        }
        sh[l] = y;
    }
    __syncthreads();
    int excl = x - v + ((w > 0) ? sh[w - 1] : 0);
    if (i < NN) g_rowptr[i] = base + excl;
}

// ---------------- fused: scatter | packX + gemm1 (rows reversed for L2 reuse) ----------------
__global__ void __launch_bounds__(512) k_scpg1(const void* __restrict__ ei, int E, int scb,
                                               const float* __restrict__ x) {
    __shared__ uint2 asv[16][NWX];
    __shared__ int   srt[16];
    __shared__ uint2 ws2[NWX * 64];
    __shared__ uint2 wv2[NWX * 64];
    int b = blockIdx.x, tid = threadIdx.x;
    if (b < scb) {                       // ---- scatter (countdown restores g_count to 0)
        int e = b * 512 + tid;
        if (e < E) {
            int is64 = g_is64;
            int dst, src;
            if (is64) {
                dst = (int)((const long long*)ei)[e];
                src = (int)((const long long*)ei)[(size_t)E + e];
            } else {
                dst = ((const int*)ei)[e];
                src = ((const int*)ei)[E + e];
            }
            int old = atomicSub(&g_count[dst], 1);
            g_adj[g_rowptr[dst] + old - 1] =
                make_int2(src, __float_as_int(g_dinv[dst] * g_dinv[src]));
        }
        return;
    }
    // ---- pack + gemm1
    int wall = g_wall[0];
    {
        unsigned* u = (unsigned*)ws2;
        for (int i = tid; i < NWX * HID; i += 512) u[i] = g_w0s[i];
        if (!wall) {
            unsigned* v = (unsigned*)wv2;
            for (int i = tid; i < NWX * HID; i += 512) v[i] = g_w0v[i];
        }
    }
    int wid = tid >> 5, l = tid & 31;
    int r0 = (PACKB - 1 - (b - scb)) * 16;   // reversed: tail of x is hottest in L2
    int r = r0 + wid;
    int tot = 0;
#pragma unroll
    for (int w = 0; w < NWX; w++) {
        int c = w * 32 + l;
        float t = __ldg(&x[(size_t)r * INF + c]) - g_cmean[c];
        unsigned sb = __ballot_sync(0xffffffffu, t > 0.0f);
        unsigned vb = __ballot_sync(0xffffffffu, t != 0.0f);
        if (l == 0) { asv[wid][w] = make_uint2(sb, vb); tot += __popc(vb); }
    }
    if (l == 0) srt[wid] = tot;
    __syncthreads();
    int tx = tid & 63, ty = tid >> 6;    // rows ty, ty+8; cols 2tx, 2tx+1
    int k00, k01, k10, k11;
    if (wall) {
        int p00 = 0, p01 = 0, p10 = 0, p11 = 0;
#pragma unroll
        for (int w = 0; w < NWX; w++) {
            uint2 aA = asv[ty][w], aB = asv[ty + 8][w];
            uint2 bb = ws2[w * 64 + tx];
            p00 += __popc(aA.y & ~(aA.x ^ bb.x));
            p01 += __popc(aA.y & ~(aA.x ^ bb.y));
            p10 += __popc(aB.y & ~(aB.x ^ bb.x));
            p11 += __popc(aB.y & ~(aB.x ^ bb.y));
        }
        int ra = srt[ty], rb = srt[ty + 8];
        k00 = 2 * p00 - ra; k01 = 2 * p01 - ra;
        k10 = 2 * p10 - rb; k11 = 2 * p11 - rb;
    } else {
        int p00 = 0, t00 = 0, p01 = 0, t01 = 0, p10 = 0, t10 = 0, p11 = 0, t11 = 0;
#pragma unroll
        for (int w = 0; w < NWX; w++) {
            uint2 aA = asv[ty][w], aB = asv[ty + 8][w];
            uint2 bb = ws2[w * 64 + tx];
            uint2 vv = wv2[w * 64 + tx];
            unsigned mA0 = aA.y & vv.x, mA1 = aA.y & vv.y;
            unsigned mB0 = aB.y & vv.x, mB1 = aB.y & vv.y;
            p00 += __popc(mA0 & ~(aA.x ^ bb.x)); t00 += __popc(mA0);
            p01 += __popc(mA1 & ~(aA.x ^ bb.y)); t01 += __popc(mA1);
            p10 += __popc(mB0 & ~(aB.x ^ bb.x)); t10 += __popc(mB0);
            p11 += __popc(mB1 & ~(aB.x ^ bb.y)); t11 += __popc(mB1);
        }
        k00 = 2 * p00 - t00; k01 = 2 * p01 - t01;
        k10 = 2 * p10 - t10; k11 = 2 * p11 - t11;
    }
    g_hk[(r0 + ty) * 64 + tx]     = __floats2half2_rn((float)k00, (float)k01);
    g_hk[(r0 + ty + 8) * 64 + tx] = __floats2half2_rn((float)k10, (float)k11);
}

// ---------------- fused: aggregate + bias + dropout + pack + next GEMM ----------------
__global__ void __launch_bounds__(256) k_agg_gemm(const float* __restrict__ bias, int layer,
                                                  unsigned fk0, unsigned fk1) {
    __shared__ uint2 ssv[8][NWH];
    __shared__ int   srt[8];
    __shared__ uint2 ws2[NWH * 64];
    __shared__ uint2 wv2[NWH * 64];
    int tid = threadIdx.x, wid = tid >> 5, l = tid & 31;
    int wall = g_wall[layer + 1];
    {
        const unsigned* wsrc = (layer == 0) ? g_w1s : g_w2s;
        const unsigned* wvsrc = (layer == 0) ? g_w1v : g_w2v;
        int nw = (layer == 0) ? NWH * HID : NWH * OUTF;
        if (tid < nw) {
            ((unsigned*)ws2)[tid] = wsrc[tid];
            if (!wall) ((unsigned*)wv2)[tid] = wvsrc[tid];
        }
        if (layer == 0 && tid + 256 < nw) {
            ((unsigned*)ws2)[tid + 256] = wsrc[tid + 256];
            if (!wall) ((unsigned*)wv2)[tid + 256] = wvsrc[tid + 256];
        }
    }
    int r = blockIdx.x * 8 + wid;
    float dr = g_dinv[r];
    float sw = dr * dr;
    const uint2* hrow = (const uint2*)((layer == 0) ? g_hk : g_hkB);
    uint2 hv = __ldg(&hrow[r * 32 + l]);
    float2 f01 = __half22float2(*(__half2*)&hv.x);
    float2 f23 = __half22float2(*(__half2*)&hv.y);
    float a0 = sw * f01.x, a1 = sw * f01.y;
    float a2 = sw * f23.x, a3 = sw * f23.y;
    int p = g_rowptr[r], pe = g_rowptr[r + 1];
    while (p + 2 <= pe) {                // unroll-2: batch 4 loads for MLP
        int2 e0 = __ldg(&g_adj[p]);
        int2 e1 = __ldg(&g_adj[p + 1]);
        uint2 v0 = __ldg(&hrow[e0.x * 32 + l]);
        uint2 v1 = __ldg(&hrow[e1.x * 32 + l]);
        float w0 = __int_as_float(e0.y);
        float w1 = __int_as_float(e1.y);
        float2 u01 = __half22float2(*(__half2*)&v0.x);
        float2 u23 = __half22float2(*(__half2*)&v0.y);
        a0 += w0 * u01.x; a1 += w0 * u01.y;
        a2 += w0 * u23.x; a3 += w0 * u23.y;
        u01 = __half22float2(*(__half2*)&v1.x);
        u23 = __half22float2(*(__half2*)&v1.y);
        a0 += w1 * u01.x; a1 += w1 * u01.y;
        a2 += w1 * u23.x; a3 += w1 * u23.y;
        p += 2;
    }
    if (p < pe) {
        int2 e0 = __ldg(&g_adj[p]);
        uint2 v0 = __ldg(&hrow[e0.x * 32 + l]);
        float w0 = __int_as_float(e0.y);
        float2 u01 = __half22float2(*(__half2*)&v0.x);
        float2 u23 = __half22float2(*(__half2*)&v0.y);
        a0 += w0 * u01.x; a1 += w0 * u01.y;
        a2 += w0 * u23.x; a3 += w0 * u23.y;
    }
    float alpha = g_alpha[layer];
    float4 b4 = __ldg(&((const float4*)bias)[l]);
    float vv[4];
    vv[0] = alpha * a0 + b4.x;
    vv[1] = alpha * a1 + b4.y;
    vv[2] = alpha * a2 + b4.z;
    vv[3] = alpha * a3 + b4.w;
    unsigned base = (unsigned)(r * HID + 4 * l);
    unsigned sn = 0, vn = 0;
#pragma unroll
    for (int k = 0; k < 4; k++) {
        unsigned o0, o1;
        tf2x32_d(fk0, fk1, 0u, base + (unsigned)k, o0, o1);
        unsigned bits = o0 ^ o1;                    // jax partitionable path
        bool keep = ((int)bits >= 0);               // uniform < 0.5
        if (vv[k] > 0.0f) sn |= 1u << k;
        if (keep && vv[k] != 0.0f) vn |= 1u << k;
    }
    int sh = 4 * (l & 7);
    unsigned s4 = sn << sh, v4 = vn << sh;
    s4 |= __shfl_xor_sync(0xffffffffu, s4, 1);  v4 |= __shfl_xor_sync(0xffffffffu, v4, 1);
    s4 |= __shfl_xor_sync(0xffffffffu, s4, 2);  v4 |= __shfl_xor_sync(0xffffffffu, v4, 2);
    s4 |= __shfl_xor_sync(0xffffffffu, s4, 4);  v4 |= __shfl_xor_sync(0xffffffffu, v4, 4);
    int t = ((l & 7) == 0) ? __popc(v4) : 0;
    t += __shfl_xor_sync(0xffffffffu, t, 8);
    t += __shfl_xor_sync(0xffffffffu, t, 16);
    if ((l & 7) == 0) ssv[wid][l >> 3] = make_uint2(s4, v4);
    if (l == 0) srt[wid] = t;
    __syncthreads();
    // ---- in-block GEMM over the 8 freshly packed rows
    if (layer == 0) {                    // 8 rows x 128 cols -> g_hkB
        int tx = tid & 63, ty = tid >> 6;   // rows ty, ty+4
        int k00, k01, k10, k11;
        if (wall) {
            int p00 = 0, p01 = 0, p10 = 0, p11 = 0;
#pragma unroll
            for (int w = 0; w < NWH; w++) {
                uint2 aA = ssv[ty][w], aB = ssv[ty + 4][w];
                uint2 bb = ws2[w * 64 + tx];
                p00 += __popc(aA.y & ~(aA.x ^ bb.x));
                p01 += __popc(aA.y & ~(aA.x ^ bb.y));
                p10 += __popc(aB.y & ~(aB.x ^ bb.x));
                p11 += __popc(aB.y & ~(aB.x ^ bb.y));
            }
            int ra = srt[ty], rb = srt[ty + 4];
            k00 = 2 * p00 - ra; k01 = 2 * p01 - ra;
            k10 = 2 * p10 - rb; k11 = 2 * p11 - rb;
        } else {
            int p00 = 0, t00 = 0, p01 = 0, t01 = 0, p10 = 0, t10 = 0, p11 = 0, t11 = 0;
#pragma unroll
            for (int w = 0; w < NWH; w++) {
                uint2 aA = ssv[ty][w], aB = ssv[ty + 4][w];
                uint2 bb = ws2[w * 64 + tx];
                uint2 vm = wv2[w * 64 + tx];
                unsigned mA0 = aA.y & vm.x, mA1 = aA.y & vm.y;
                unsigned mB0 = aB.y & vm.x, mB1 = aB.y & vm.y;
                p00 += __popc(mA0 & ~(aA.x ^ bb.x)); t00 += __popc(mA0);
                p01 += __popc(mA1 & ~(aA.x ^ bb.y)); t01 += __popc(mA1);
                p10 += __popc(mB0 & ~(aB.x ^ bb.x)); t10 += __popc(mB0);
                p11 += __popc(mB1 & ~(aB.x ^ bb.y)); t11 += __popc(mB1);
            }
            k00 = 2 * p00 - t00; k01 = 2 * p01 - t01;
            k10 = 2 * p10 - t10; k11 = 2 * p11 - t11;
        }
        int r0 = blockIdx.x * 8;
        g_hkB[(r0 + ty) * 64 + tx]     = __floats2half2_rn((float)k00, (float)k01);
        g_hkB[(r0 + ty + 4) * 64 + tx] = __floats2half2_rn((float)k10, (float)k11);
    } else {                             // 8 rows x 40 cols -> g_h3k
        if (tid < 160) {
            int ty = tid / 20, tx = tid % 20;  // cols 2tx, 2tx+1
            int k0, k1;
            if (wall) {
                int p0 = 0, p1 = 0;
#pragma unroll
                for (int w = 0; w < NWH; w++) {
                    uint2 a = ssv[ty][w];
                    uint2 bb = ws2[w * 20 + tx];
                    p0 += __popc(a.y & ~(a.x ^ bb.x));
                    p1 += __popc(a.y & ~(a.x ^ bb.y));
                }
                int rt = srt[ty];
                k0 = 2 * p0 - rt; k1 = 2 * p1 - rt;
            } else {
                int p0 = 0, t0 = 0, p1 = 0, t1 = 0;
#pragma unroll
                for (int w = 0; w < NWH; w++) {
                    uint2 a = ssv[ty][w];
                    uint2 bb = ws2[w * 20 + tx];
                    uint2 vm = wv2[w * 20 + tx];
                    unsigned m0 = a.y & vm.x, m1 = a.y & vm.y;
                    p0 += __popc(m0 & ~(a.x ^ bb.x)); t0 += __popc(m0);
                    p1 += __popc(m1 & ~(a.x ^ bb.y)); t1 += __popc(m1);
                }
                k0 = 2 * p0 - t0; k1 = 2 * p1 - t1;
            }
            g_h3k[(blockIdx.x * 8 + ty) * 20 + tx] = __floats2half2_rn((float)k0, (float)k1);
        }
    }
}

// ---------------- final aggregate + bias + log_softmax ----------------
__global__ void __launch_bounds__(256) k_agg_final(const float* __restrict__ bias,
                                                   float* __restrict__ out) {
    int wid = threadIdx.x >> 5, l = threadIdx.x & 31;
    int r = blockIdx.x * 8 + wid;
    float dr = g_dinv[r];
    float sw = dr * dr;
    bool act = (l < 20);
    float a0 = 0.0f, a1 = 0.0f;
    if (act) {
        float2 f = __half22float2(__ldg(&g_h3k[r * 20 + l]));
        a0 = sw * f.x; a1 = sw * f.y;
    }
    int p = g_rowptr[r], pe = g_rowptr[r + 1];
    while (p + 2 <= pe) {
        int2 e0 = __ldg(&g_adj[p]);
        int2 e1 = __ldg(&g_adj[p + 1]);
        __half2 u0 = act ? __ldg(&g_h3k[e0.x * 20 + l]) : __half2();
        __half2 u1 = act ? __ldg(&g_h3k[e1.x * 20 + l]) : __half2();
        float w0 = __int_as_float(e0.y);
        float w1 = __int_as_float(e1.y);
        float2 f0 = __half22float2(u0);
        float2 f1 = __half22float2(u1);
        a0 += w0 * f0.x; a1 += w0 * f0.y;
        a0 += w1 * f1.x; a1 += w1 * f1.y;
        p += 2;
    }
    if (p < pe) {
        int2 e0 = __ldg(&g_adj[p]);
        __half2 u0 = act ? __ldg(&g_h3k[e0.x * 20 + l]) : __half2();
        float w0 = __int_as_float(e0.y);
        float2 f0 = __half22float2(u0);
        a0 += w0 * f0.x; a1 += w0 * f0.y;
    }
    float alpha = g_alpha[2];
    float v0 = 0.0f, v1 = 0.0f;
    if (act) {
        float2 b2v = __ldg(&((const float2*)bias)[l]);
        v0 = alpha * a0 + b2v.x;
        v1 = alpha * a1 + b2v.y;
    }
    float m = act ? fmaxf(v0, v1) : -3.4e38f;
    for (int off = 16; off; off >>= 1) m = fmaxf(m, __shfl_xor_sync(0xffffffffu, m, off));
    float s = act ? (expf(v0 - m) + expf(v1 - m)) : 0.0f;
    for (int off = 16; off; off >>= 1) s += __shfl_xor_sync(0xffffffffu, s, off);
    float lse = m + logf(s);
    if (act) {
        float2 o; o.x = v0 - lse; o.y = v1 - lse;
        ((float2*)out)[r * 20 + l] = o;
    }
}

// ---------------- launch ----------------
extern "C" void kernel_launch(void* const* d_in, const int* in_sizes, int n_in,
                              void* d_out, int out_size) {
    const float* x  = (const float*)d_in[0];
    const void*  ei = d_in[1];
    const float* w0 = (const float*)d_in[2];
    const float* b0 = (const float*)d_in[3];
    const float* w1 = (const float*)d_in[4];
    const float* b1 = (const float*)d_in[5];
    const float* w2 = (const float*)d_in[6];
    const float* b2 = (const float*)d_in[7];
    float* out = (float*)d_out;
    int E = in_sizes[1] / 2;

    // dropout fold-in keys: fold_in(key(42), i) = threefry((0,42), (0,i))
    unsigned fk[2][2];
    for (int i = 0; i < 2; i++) tf2x32_h(0u, 42u, 0u, (unsigned)i, fk[i][0], fk[i][1]);

    k_pre<<<CSBLK + PWB + (E + 255) / 256, 256>>>(x, w0, w1, w2, ei, E);
    k_scanA<<<53, 1024>>>(ei);
    k_scanB<<<49, 1024>>>();
    int scb = (E + 511) / 512;
    k_scpg1<<<scb + PACKB, 512>>>(ei, E, scb, x);
    k_agg_gemm<<<NN / 8, 256>>>(b0, 0, fk[0][0], fk[0][1]);
    k_agg_gemm<<<NN / 8, 256>>>(b1, 1, fk[1][0], fk[1][1]);
    k_agg_final<<<NN / 8, 256>>>(b2, out);
}